// round 1
// baseline (speedup 1.0000x reference)
#include <cuda_runtime.h>

#define N_NODES 4096
#define IN_F 512
#define OUT_F 64
#define HEADS 8
#define ALPHA 0.2f

// ---------------- scratch (device globals; no allocation) ----------------
__device__ float g_Wh[HEADS * N_NODES * OUT_F];          // 8 MB  [h][n][o]
__device__ float g_f1[HEADS * N_NODES];
__device__ float g_f2[HEADS * N_NODES];
__device__ float g_P1[HEADS * N_NODES];                  // exp(f1)
__device__ float g_P2[HEADS * N_NODES];                  // exp(f2)
__device__ float g_Q1[HEADS * N_NODES];                  // exp(alpha*f1)
__device__ float g_Q2[HEADS * N_NODES];                  // exp(alpha*f2)
__device__ unsigned g_adjbits[N_NODES * (N_NODES / 32)]; // 2 MB bitmask

// ---------------- packed f32x2 helpers ----------------
__device__ __forceinline__ unsigned long long fma2(unsigned long long a,
                                                   unsigned long long b,
                                                   unsigned long long c) {
    unsigned long long d;
    asm("fma.rn.f32x2 %0, %1, %2, %3;" : "=l"(d) : "l"(a), "l"(b), "l"(c));
    return d;
}
__device__ __forceinline__ unsigned long long pack2(float x, float y) {
    unsigned long long d;
    asm("mov.b64 %0, {%1, %2};" : "=l"(d) : "f"(x), "f"(y));
    return d;
}
__device__ __forceinline__ void unpack2(unsigned long long v, float& lo, float& hi) {
    asm("mov.b64 {%0, %1}, %2;" : "=f"(lo), "=f"(hi) : "l"(v));
}

// ---------------- kernel C: bit-pack adjacency ----------------
__global__ void bitpack_kernel(const int* __restrict__ adj) {
    int gid = blockIdx.x * blockDim.x + threadIdx.x;
    unsigned m = __ballot_sync(0xffffffffu, adj[gid] > 0);
    if ((threadIdx.x & 31) == 0) g_adjbits[gid >> 5] = m;
}

// ---------------- kernel A: Wh = x @ W (per head) ----------------
// grid (64, 8), block 128. BM=64 (n), BN=64 (o), BK=32. micro 4x8 (packed o-pairs).
__global__ __launch_bounds__(128) void wh_gemm_kernel(const float* __restrict__ x,
                                                      const float* __restrict__ W) {
    const int h = blockIdx.y;
    const int nbase = blockIdx.x * 64;
    const int t = threadIdx.x;
    const int ty = t >> 3;   // 0..15 -> rows ty*4..+3
    const int tx = t & 7;    // 0..7  -> cols tx*8..+7

    __shared__ float xS[32][68];     // [k][n], padded for 16B-aligned LDS.128
    __shared__ float wS[32 * 64];    // [k][o]

    unsigned long long acc[4][4];
#pragma unroll
    for (int i = 0; i < 4; i++)
#pragma unroll
        for (int j = 0; j < 4; j++) acc[i][j] = 0ull;

    for (int kt = 0; kt < IN_F / 32; kt++) {
        // stage x tile (transpose to k-major)
#pragma unroll
        for (int i = 0; i < 4; i++) {
            int f = t + i * 128;            // 512 float4s
            int nl = f >> 3, kq = f & 7;
            float4 v = *(const float4*)&x[(nbase + nl) * IN_F + kt * 32 + kq * 4];
            xS[kq * 4 + 0][nl] = v.x;
            xS[kq * 4 + 1][nl] = v.y;
            xS[kq * 4 + 2][nl] = v.z;
            xS[kq * 4 + 3][nl] = v.w;
        }
        // stage W tile (already k-major, o contiguous)
        const float* Wb = W + h * IN_F * OUT_F + kt * 32 * OUT_F;
#pragma unroll
        for (int i = 0; i < 4; i++) {
            int f = t + i * 128;
            *(float4*)&wS[f * 4] = *(const float4*)&Wb[f * 4];
        }
        __syncthreads();
#pragma unroll
        for (int k = 0; k < 32; k++) {
            float4 av = *(const float4*)&xS[k][ty * 4];
            unsigned long long ad[4];
            ad[0] = pack2(av.x, av.x);
            ad[1] = pack2(av.y, av.y);
            ad[2] = pack2(av.z, av.z);
            ad[3] = pack2(av.w, av.w);
            const ulonglong2* bp = (const ulonglong2*)&wS[k * 64 + tx * 8];
            ulonglong2 b01 = bp[0];
            ulonglong2 b23 = bp[1];
            unsigned long long b[4] = {b01.x, b01.y, b23.x, b23.y};
#pragma unroll
            for (int i = 0; i < 4; i++)
#pragma unroll
                for (int j = 0; j < 4; j++) acc[i][j] = fma2(ad[i], b[j], acc[i][j]);
        }
        __syncthreads();
    }
    // write Wh[h][n][o]
#pragma unroll
    for (int i = 0; i < 4; i++) {
        int row = nbase + ty * 4 + i;
        unsigned long long* op =
            (unsigned long long*)&g_Wh[(h * N_NODES + row) * OUT_F + tx * 8];
#pragma unroll
        for (int j = 0; j < 4; j++) op[j] = acc[i][j];
    }
}

// ---------------- kernel B: f1/f2 + exp tables ----------------
// one warp per (h, n)
__global__ void attn_vec_kernel(const float* __restrict__ a1,
                                const float* __restrict__ a2) {
    int gw = (blockIdx.x * blockDim.x + threadIdx.x) >> 5;
    int lane = threadIdx.x & 31;
    if (gw >= HEADS * N_NODES) return;
    int h = gw >> 12;
    int n = gw & (N_NODES - 1);
    const float* whp = &g_Wh[(h * N_NODES + n) * OUT_F];
    float w0 = whp[lane], w1 = whp[lane + 32];
    float s1 = w0 * a1[h * OUT_F + lane] + w1 * a1[h * OUT_F + lane + 32];
    float s2 = w0 * a2[h * OUT_F + lane] + w1 * a2[h * OUT_F + lane + 32];
#pragma unroll
    for (int off = 16; off; off >>= 1) {
        s1 += __shfl_xor_sync(0xffffffffu, s1, off);
        s2 += __shfl_xor_sync(0xffffffffu, s2, off);
    }
    if (lane == 0) {
        int idx = h * N_NODES + n;
        g_f1[idx] = s1;
        g_P1[idx] = expf(s1);
        g_Q1[idx] = expf(ALPHA * s1);
        g_f2[idx] = s2;
        g_P2[idx] = expf(s2);
        g_Q2[idx] = expf(ALPHA * s2);
    }
}

// ---------------- kernel D: fused masked softmax-weighted aggregation ----------------
// out[n, h*64+o] = (1/D[h,n]) * sum_m w[h,n,m] * Wh[h,m,o]
// w = adj ? ((f1+f2>0) ? P1*P2 : Q1*Q2) : 0 ;  D = sum_m w
// grid (64, 8), block 128. BM=64 rows, BN=64 outputs, BK=32 m per tile.
__global__ __launch_bounds__(128) void gat_main_kernel(float* __restrict__ out) {
    const int h = blockIdx.y;
    const int nbase = blockIdx.x * 64;
    const int t = threadIdx.x;
    const int ty = t >> 3;   // 0..15 -> rows ty*4..+3
    const int tx = t & 7;    // 0..7  -> outputs tx*8..+7

    __shared__ float wS[32 * 64];    // [mm][r] attention weights
    __shared__ float whS[32 * 64];   // [mm][o] Wh tile
    __shared__ float rowF1[64], rowP1[64], rowQ1[64];
    __shared__ float colF2[32], colP2[32], colQ2[32];
    __shared__ unsigned adjwS[64];
    __shared__ float Dsh[128];

    if (t < 64) {
        int idx = h * N_NODES + nbase + t;
        rowF1[t] = g_f1[idx];
        rowP1[t] = g_P1[idx];
        rowQ1[t] = g_Q1[idx];
    }
    __syncthreads();

    const int r0 = t & 63;            // w-gen: fixed row per thread
    const float mF1 = rowF1[r0];
    const float mP1 = rowP1[r0];
    const float mQ1 = rowQ1[r0];
    const int mhalf = t >> 6;         // 0 or 1 -> even/odd mm

    unsigned long long acc[4][4];
#pragma unroll
    for (int i = 0; i < 4; i++)
#pragma unroll
        for (int j = 0; j < 4; j++) acc[i][j] = 0ull;
    float Dacc = 0.f;

    for (int mt = 0; mt < N_NODES / 32; mt++) {
        // stage per-tile scalars
        if (t < 64) {
            adjwS[t] = g_adjbits[(nbase + t) * (N_NODES / 32) + mt];
        } else if (t < 96) {
            int m = h * N_NODES + mt * 32 + (t - 64);
            colF2[t - 64] = g_f2[m];
            colP2[t - 64] = g_P2[m];
            colQ2[t - 64] = g_Q2[m];
        }
        __syncthreads();

        // generate attention-weight tile + accumulate denominator
        unsigned aw = adjwS[r0];
#pragma unroll
        for (int i = 0; i < 16; i++) {
            int mm = mhalf + i * 2;
            float w = 0.f;
            if ((aw >> mm) & 1u) {
                float f2v = colF2[mm];
                w = (mF1 + f2v > 0.f) ? (mP1 * colP2[mm]) : (mQ1 * colQ2[mm]);
            }
            wS[mm * 64 + r0] = w;
            Dacc += w;
        }
        // stage Wh tile
        const float* whB = &g_Wh[h * N_NODES * OUT_F + mt * 32 * OUT_F];
#pragma unroll
        for (int i = 0; i < 4; i++) {
            int f = t + i * 128;
            *(float4*)&whS[f * 4] = *(const float4*)&whB[f * 4];
        }
        __syncthreads();

        // FMA: acc[r][o-pair] += w[r][mm] * Wh[mm][o-pair]
#pragma unroll
        for (int k = 0; k < 32; k++) {
            float4 av = *(const float4*)&wS[k * 64 + ty * 4];
            unsigned long long ad[4];
            ad[0] = pack2(av.x, av.x);
            ad[1] = pack2(av.y, av.y);
            ad[2] = pack2(av.z, av.z);
            ad[3] = pack2(av.w, av.w);
            const ulonglong2* bp = (const ulonglong2*)&whS[k * 64 + tx * 8];
            ulonglong2 b01 = bp[0];
            ulonglong2 b23 = bp[1];
            unsigned long long b[4] = {b01.x, b01.y, b23.x, b23.y};
#pragma unroll
            for (int i = 0; i < 4; i++)
#pragma unroll
                for (int j = 0; j < 4; j++) acc[i][j] = fma2(ad[i], b[j], acc[i][j]);
        }
        __syncthreads();
    }

    // reduce denominators (2 partial sums per row)
    Dsh[t] = Dacc;
    __syncthreads();
    if (t < 64) Dsh[t] = 1.0f / (Dsh[t] + Dsh[t + 64]);
    __syncthreads();

    // normalize + write out[n, h*64+o]
#pragma unroll
    for (int i = 0; i < 4; i++) {
        int row = nbase + ty * 4 + i;
        float inv = Dsh[ty * 4 + i];
        float* op = &out[row * (HEADS * OUT_F) + h * OUT_F + tx * 8];
#pragma unroll
        for (int j = 0; j < 4; j++) {
            float lo, hi;
            unpack2(acc[i][j], lo, hi);
            float2 v = make_float2(lo * inv, hi * inv);
            *(float2*)&op[j * 2] = v;
        }
    }
}

// ---------------- launch ----------------
extern "C" void kernel_launch(void* const* d_in, const int* in_sizes, int n_in,
                              void* d_out, int out_size) {
    const float* x   = (const float*)d_in[0];   // [4096, 512]
    const int*   adj = (const int*)d_in[1];     // [4096, 4096]
    const float* W   = (const float*)d_in[2];   // [8, 512, 64]
    const float* a1  = (const float*)d_in[3];   // [8, 64]
    const float* a2  = (const float*)d_in[4];   // [8, 64]
    float* out = (float*)d_out;                 // [4096, 512]

    bitpack_kernel<<<(N_NODES * N_NODES) / 256, 256>>>(adj);

    dim3 gA(N_NODES / 64, HEADS);
    wh_gemm_kernel<<<gA, 128>>>(x, W);

    attn_vec_kernel<<<(HEADS * N_NODES * 32) / 256, 256>>>(a1, a2);

    dim3 gD(N_NODES / 64, HEADS);
    gat_main_kernel<<<gD, 128>>>(out);
}

// round 4
// speedup vs baseline: 2.1639x; 2.1639x over previous
#include <cuda_runtime.h>
#include <cuda_bf16.h>
#include <cstdint>

#define N_NODES 4096
#define IN_F 512
#define OUT_F 64
#define HEADS 8
#define ALPHA 0.2f

#define RT 128                 // rows per CTA (gat kernel)
#define KC 32                  // m per chunk
#define NCH (N_NODES / KC)     // 128 chunks
#define ASTR 40                // padded bf16 stride (80 B) -> conflict-free ldmatrix
#define BSTR 40

// ---------------- scratch (device globals; no allocation) ----------------
__device__ __align__(16) float g_Wh[HEADS * N_NODES * OUT_F];             // 8 MB [h][n][o]
__device__ float g_f1[HEADS * N_NODES];
__device__ float g_f2[HEADS * N_NODES];
__device__ float g_P1[HEADS * N_NODES];
__device__ float g_P2[HEADS * N_NODES];
__device__ float g_Q1[HEADS * N_NODES];
__device__ float g_Q2[HEADS * N_NODES];
__device__ unsigned g_adjbits[N_NODES * (N_NODES / 32)];                  // 2 MB
__device__ __align__(16) __nv_bfloat16 g_WhT_hi[HEADS * OUT_F * N_NODES]; // 4 MB [h][o][m]
__device__ __align__(16) __nv_bfloat16 g_WhT_lo[HEADS * OUT_F * N_NODES]; // 4 MB

// ---------------- helpers ----------------
__device__ __forceinline__ unsigned long long fma2(unsigned long long a,
                                                   unsigned long long b,
                                                   unsigned long long c) {
    unsigned long long d;
    asm("fma.rn.f32x2 %0, %1, %2, %3;" : "=l"(d) : "l"(a), "l"(b), "l"(c));
    return d;
}
__device__ __forceinline__ unsigned long long pack2(float x, float y) {
    unsigned long long d;
    asm("mov.b64 %0, {%1, %2};" : "=l"(d) : "f"(x), "f"(y));
    return d;
}
__device__ __forceinline__ uint32_t smem_u32(const void* p) {
    uint32_t a;
    asm("{ .reg .u64 t; cvta.to.shared.u64 t, %1; cvt.u32.u64 %0, t; }" : "=r"(a) : "l"(p));
    return a;
}
__device__ __forceinline__ void cp16(uint32_t dst, const void* src) {
    asm volatile("cp.async.cg.shared.global [%0], [%1], 16;" :: "r"(dst), "l"(src) : "memory");
}
__device__ __forceinline__ void cp_commit() {
    asm volatile("cp.async.commit_group;" ::: "memory");
}
template <int N>
__device__ __forceinline__ void cp_wait() {
    asm volatile("cp.async.wait_group %0;" :: "n"(N) : "memory");
}
__device__ __forceinline__ void ldm4(uint32_t* r, uint32_t addr) {
    asm volatile("ldmatrix.sync.aligned.m8n8.x4.shared.b16 {%0,%1,%2,%3}, [%4];"
                 : "=r"(r[0]), "=r"(r[1]), "=r"(r[2]), "=r"(r[3]) : "r"(addr) : "memory");
}
__device__ __forceinline__ void mma_bf16(float* c, const uint32_t* a, uint32_t b0,
                                         uint32_t b1) {
    asm("mma.sync.aligned.m16n8k16.row.col.f32.bf16.bf16.f32 "
        "{%0,%1,%2,%3}, {%4,%5,%6,%7}, {%8,%9}, {%0,%1,%2,%3};"
        : "+f"(c[0]), "+f"(c[1]), "+f"(c[2]), "+f"(c[3])
        : "r"(a[0]), "r"(a[1]), "r"(a[2]), "r"(a[3]), "r"(b0), "r"(b1));
}

// ---------------- kernel C: bit-pack adjacency ----------------
__global__ void bitpack_kernel(const int* __restrict__ adj) {
    int gid = blockIdx.x * blockDim.x + threadIdx.x;
    unsigned m = __ballot_sync(0xffffffffu, adj[gid] > 0);
    if ((threadIdx.x & 31) == 0) g_adjbits[gid >> 5] = m;
}

// ---------------- kernel A: Wh = x @ W (per head) ----------------
__global__ __launch_bounds__(128) void wh_gemm_kernel(const float* __restrict__ x,
                                                      const float* __restrict__ W) {
    const int h = blockIdx.y;
    const int nbase = blockIdx.x * 64;
    const int t = threadIdx.x;
    const int ty = t >> 3;
    const int tx = t & 7;

    __shared__ float xS[32][68];
    __shared__ float wS[32 * 64];

    unsigned long long acc[4][4];
#pragma unroll
    for (int i = 0; i < 4; i++)
#pragma unroll
        for (int j = 0; j < 4; j++) acc[i][j] = 0ull;

    for (int kt = 0; kt < IN_F / 32; kt++) {
#pragma unroll
        for (int i = 0; i < 4; i++) {
            int f = t + i * 128;
            int nl = f >> 3, kq = f & 7;
            float4 v = *(const float4*)&x[(nbase + nl) * IN_F + kt * 32 + kq * 4];
            xS[kq * 4 + 0][nl] = v.x;
            xS[kq * 4 + 1][nl] = v.y;
            xS[kq * 4 + 2][nl] = v.z;
            xS[kq * 4 + 3][nl] = v.w;
        }
        const float* Wb = W + h * IN_F * OUT_F + kt * 32 * OUT_F;
#pragma unroll
        for (int i = 0; i < 4; i++) {
            int f = t + i * 128;
            *(float4*)&wS[f * 4] = *(const float4*)&Wb[f * 4];
        }
        __syncthreads();
#pragma unroll
        for (int k = 0; k < 32; k++) {
            float4 av = *(const float4*)&xS[k][ty * 4];
            unsigned long long ad[4];
            ad[0] = pack2(av.x, av.x);
            ad[1] = pack2(av.y, av.y);
            ad[2] = pack2(av.z, av.z);
            ad[3] = pack2(av.w, av.w);
            const ulonglong2* bp = (const ulonglong2*)&wS[k * 64 + tx * 8];
            ulonglong2 b01 = bp[0];
            ulonglong2 b23 = bp[1];
            unsigned long long b[4] = {b01.x, b01.y, b23.x, b23.y};
#pragma unroll
            for (int i = 0; i < 4; i++)
#pragma unroll
                for (int j = 0; j < 4; j++) acc[i][j] = fma2(ad[i], b[j], acc[i][j]);
        }
        __syncthreads();
    }
#pragma unroll
    for (int i = 0; i < 4; i++) {
        int row = nbase + ty * 4 + i;
        unsigned long long* op =
            (unsigned long long*)&g_Wh[(h * N_NODES + row) * OUT_F + tx * 8];
#pragma unroll
        for (int j = 0; j < 4; j++) op[j] = acc[i][j];
    }
}

// ---------------- kernel B: f1/f2 + exp tables ----------------
__global__ void attn_vec_kernel(const float* __restrict__ a1,
                                const float* __restrict__ a2) {
    int gw = (blockIdx.x * blockDim.x + threadIdx.x) >> 5;
    int lane = threadIdx.x & 31;
    if (gw >= HEADS * N_NODES) return;
    int h = gw >> 12;
    int n = gw & (N_NODES - 1);
    const float* whp = &g_Wh[(h * N_NODES + n) * OUT_F];
    float w0 = whp[lane], w1 = whp[lane + 32];
    float s1 = w0 * a1[h * OUT_F + lane] + w1 * a1[h * OUT_F + lane + 32];
    float s2 = w0 * a2[h * OUT_F + lane] + w1 * a2[h * OUT_F + lane + 32];
#pragma unroll
    for (int off = 16; off; off >>= 1) {
        s1 += __shfl_xor_sync(0xffffffffu, s1, off);
        s2 += __shfl_xor_sync(0xffffffffu, s2, off);
    }
    if (lane == 0) {
        int idx = h * N_NODES + n;
        g_f1[idx] = s1;
        g_P1[idx] = expf(s1);
        g_Q1[idx] = expf(ALPHA * s1);
        g_f2[idx] = s2;
        g_P2[idx] = expf(s2);
        g_Q2[idx] = expf(ALPHA * s2);
    }
}

// ---------------- kernel A2: transpose + bf16 split of Wh ----------------
__global__ __launch_bounds__(256) void whT_split_kernel() {
    __shared__ float T[64 * 65];
    const int h = blockIdx.y;
    const int mb = blockIdx.x * 64;
    const int t = threadIdx.x;
    const float* src = g_Wh + ((size_t)h * N_NODES + mb) * OUT_F;
#pragma unroll
    for (int i = 0; i < 16; i++) {
        int lin = t + i * 256;
        int m = lin >> 6, o = lin & 63;
        T[m * 65 + o] = src[lin];
    }
    __syncthreads();
#pragma unroll
    for (int i = 0; i < 8; i++) {
        int lin = t + i * 256;
        int o = lin >> 5, mp = lin & 31;
        float w0 = T[(2 * mp) * 65 + o];
        float w1 = T[(2 * mp + 1) * 65 + o];
        __nv_bfloat16 h0 = __float2bfloat16(w0), h1 = __float2bfloat16(w1);
        __nv_bfloat16 l0 = __float2bfloat16(w0 - __bfloat162float(h0));
        __nv_bfloat16 l1 = __float2bfloat16(w1 - __bfloat162float(h1));
        unsigned hw = (unsigned)__bfloat16_as_ushort(h0) |
                      ((unsigned)__bfloat16_as_ushort(h1) << 16);
        unsigned lw = (unsigned)__bfloat16_as_ushort(l0) |
                      ((unsigned)__bfloat16_as_ushort(l1) << 16);
        size_t dst = ((size_t)h * OUT_F + o) * N_NODES + mb + 2 * mp;
        *reinterpret_cast<unsigned*>(&g_WhT_hi[dst]) = hw;
        *reinterpret_cast<unsigned*>(&g_WhT_lo[dst]) = lw;
    }
}

// ---------------- kernel D: HMMA fused masked-softmax aggregation ----------------
__global__ __launch_bounds__(256, 2) void gat_mma_kernel(float* __restrict__ out) {
    __shared__ __align__(16) __nv_bfloat16 A_hi[RT * ASTR];        // 10240 B
    __shared__ __align__(16) __nv_bfloat16 A_lo[RT * ASTR];
    __shared__ __align__(16) __nv_bfloat16 Bt[2][2][64 * BSTR];    // [buf][hi/lo][o][m]
    __shared__ float Dsh[256];

    const int t = threadIdx.x;
    const int wid = t >> 5, lane = t & 31;
    const int h = blockIdx.y;
    const int nbase = blockIdx.x * RT;
    const int hN = h * N_NODES;

    const int r = t >> 1;
    const int half = t & 1;
    const int grow = nbase + r;
    const float F1r = g_f1[hN + grow];
    const float P1r = g_P1[hN + grow];
    const float Q1r = g_Q1[hN + grow];
    const unsigned* adjrow = g_adjbits + (size_t)grow * (N_NODES / 32);
    float Dacc = 0.f;

    const uint32_t aHiB = smem_u32(A_hi);
    const uint32_t aLoB = smem_u32(A_lo);
    const uint32_t bB00 = smem_u32(Bt[0][0]);   // buf0 hi
    const uint32_t bB01 = smem_u32(Bt[0][1]);   // buf0 lo
    const uint32_t bB10 = smem_u32(Bt[1][0]);   // buf1 hi
    const uint32_t bB11 = smem_u32(Bt[1][1]);   // buf1 lo

    const __nv_bfloat16* whTh = g_WhT_hi + ((size_t)h * OUT_F) * N_NODES;
    const __nv_bfloat16* whTl = g_WhT_lo + ((size_t)h * OUT_F) * N_NODES;

    // B staging: idx in [0,512): prec = idx>>8, o-row = (idx>>2)&63, quad = idx&3
    const int i0p = (t * 2) >> 8, i0r = ((t * 2) >> 2) & 63, i0q = (t * 2) & 3;
    const int i1p = (t * 2 + 1) >> 8, i1r = ((t * 2 + 1) >> 2) & 63, i1q = (t * 2 + 1) & 3;
    const __nv_bfloat16* s0base = (i0p ? whTl : whTh) + (size_t)i0r * N_NODES + i0q * 8;
    const __nv_bfloat16* s1base = (i1p ? whTl : whTh) + (size_t)i1r * N_NODES + i1q * 8;
    const uint32_t d0off = (uint32_t)(i0r * (BSTR * 2) + i0q * 16);
    const uint32_t d1off = (uint32_t)(i1r * (BSTR * 2) + i1q * 16);
    // per-buffer dst bases for this thread's two elements
    const uint32_t dst0buf[2] = {(i0p ? bB01 : bB00) + d0off, (i0p ? bB11 : bB10) + d0off};
    const uint32_t dst1buf[2] = {(i1p ? bB01 : bB00) + d1off, (i1p ? bB11 : bB10) + d1off};

    // prologue: stage chunk 0 into buffer 0 (FIX: both elements -> buffer 0)
    cp16(dst0buf[0], s0base);
    cp16(dst1buf[0], s1base);
    cp_commit();

    float acc[8][4];
#pragma unroll
    for (int j = 0; j < 8; j++)
#pragma unroll
        for (int q = 0; q < 4; q++) acc[j][q] = 0.f;

    const uint32_t aOffHi = aHiB + (16 * wid + (lane & 15)) * (ASTR * 2) + (lane >> 4) * 16;
    const uint32_t aOffLo = aLoB + (16 * wid + (lane & 15)) * (ASTR * 2) + (lane >> 4) * 16;
    const uint32_t bRowOff = (lane & 7) * (BSTR * 2) + (lane >> 3) * 16;

    for (int c = 0; c < NCH; c++) {
        const int p = c & 1;
        if (c + 1 < NCH) {
            const int mb2 = (c + 1) * KC;
            const int pn = (c + 1) & 1;
            cp16(dst0buf[pn], s0base + mb2);
            cp16(dst1buf[pn], s1base + mb2);
            cp_commit();
        }

        // ---- w-gen: 16 m per thread, bf16 hi/lo ----
        {
            const int mb = c * KC + half * 16;
            const unsigned aw = adjrow[c];
            unsigned hiw[8], low[8];
#pragma unroll
            for (int q = 0; q < 4; q++) {
                float4 f2v = *(const float4*)(g_f2 + hN + mb + q * 4);
                float4 p2v = *(const float4*)(g_P2 + hN + mb + q * 4);
                float4 q2v = *(const float4*)(g_Q2 + hN + mb + q * 4);
                float fv[4] = {f2v.x, f2v.y, f2v.z, f2v.w};
                float pv[4] = {p2v.x, p2v.y, p2v.z, p2v.w};
                float qv[4] = {q2v.x, q2v.y, q2v.z, q2v.w};
                float wv[4];
#pragma unroll
                for (int e = 0; e < 4; e++) {
                    int bit = half * 16 + q * 4 + e;
                    float pos = F1r + fv[e];
                    float w = (pos > 0.f) ? (P1r * pv[e]) : (Q1r * qv[e]);
                    w = ((aw >> bit) & 1u) ? w : 0.f;
                    Dacc += w;
                    wv[e] = w;
                }
#pragma unroll
                for (int e = 0; e < 4; e += 2) {
                    float2 wp = make_float2(wv[e], wv[e + 1]);
                    __nv_bfloat162 h2 = __float22bfloat162_rn(wp);
                    float2 hf = __bfloat1622float2(h2);
                    __nv_bfloat162 l2 = __float22bfloat162_rn(
                        make_float2(wp.x - hf.x, wp.y - hf.y));
                    hiw[q * 2 + e / 2] = *reinterpret_cast<unsigned*>(&h2);
                    low[q * 2 + e / 2] = *reinterpret_cast<unsigned*>(&l2);
                }
            }
            uint4* dhA = (uint4*)(A_hi + r * ASTR + half * 16);
            uint4* dlA = (uint4*)(A_lo + r * ASTR + half * 16);
            dhA[0] = make_uint4(hiw[0], hiw[1], hiw[2], hiw[3]);
            dhA[1] = make_uint4(hiw[4], hiw[5], hiw[6], hiw[7]);
            dlA[0] = make_uint4(low[0], low[1], low[2], low[3]);
            dlA[1] = make_uint4(low[4], low[5], low[6], low[7]);
        }

        if (c + 1 < NCH) cp_wait<1>();
        else cp_wait<0>();
        __syncthreads();

        // ---- MMA ----
        uint32_t afh[2][4], afl[2][4];
        ldm4(afh[0], aOffHi);
        ldm4(afh[1], aOffHi + 32);
        ldm4(afl[0], aOffLo);
        ldm4(afl[1], aOffLo + 32);
        const uint32_t bHi = p ? bB10 : bB00;
        const uint32_t bLo = p ? bB11 : bB01;
#pragma unroll
        for (int j = 0; j < 8; j++) {
            uint32_t bh[4], bl[4];
            ldm4(bh, bHi + j * 8 * (BSTR * 2) + bRowOff);
            ldm4(bl, bLo + j * 8 * (BSTR * 2) + bRowOff);
            mma_bf16(acc[j], afh[0], bh[0], bh[1]);
            mma_bf16(acc[j], afh[0], bl[0], bl[1]);
            mma_bf16(acc[j], afl[0], bh[0], bh[1]);
            mma_bf16(acc[j], afh[1], bh[2], bh[3]);
            mma_bf16(acc[j], afh[1], bl[2], bl[3]);
            mma_bf16(acc[j], afl[1], bh[2], bh[3]);
        }
        __syncthreads();
    }

    Dsh[t] = Dacc;
    __syncthreads();

    const int g = lane >> 2;
    const int row0 = 16 * wid + g;
    const int row1 = row0 + 8;
    const float inv0 = 1.0f / (Dsh[2 * row0] + Dsh[2 * row0 + 1]);
    const float inv1 = 1.0f / (Dsh[2 * row1] + Dsh[2 * row1 + 1]);
    float* o0 = out + (size_t)(nbase + row0) * (HEADS * OUT_F) + h * OUT_F + (lane & 3) * 2;
    float* o1 = out + (size_t)(nbase + row1) * (HEADS * OUT_F) + h * OUT_F + (lane & 3) * 2;
#pragma unroll
    for (int j = 0; j < 8; j++) {
        *(float2*)(o0 + j * 8) = make_float2(acc[j][0] * inv0, acc[j][1] * inv0);
        *(float2*)(o1 + j * 8) = make_float2(acc[j][2] * inv1, acc[j][3] * inv1);
    }
}

// ---------------- launch ----------------
extern "C" void kernel_launch(void* const* d_in, const int* in_sizes, int n_in,
                              void* d_out, int out_size) {
    const float* x   = (const float*)d_in[0];
    const int*   adj = (const int*)d_in[1];
    const float* W   = (const float*)d_in[2];
    const float* a1  = (const float*)d_in[3];
    const float* a2  = (const float*)d_in[4];
    float* out = (float*)d_out;

    bitpack_kernel<<<(N_NODES * N_NODES) / 256, 256>>>(adj);

    dim3 gA(N_NODES / 64, HEADS);
    wh_gemm_kernel<<<gA, 128>>>(x, W);

    attn_vec_kernel<<<(HEADS * N_NODES * 32) / 256, 256>>>(a1, a2);

    dim3 gT(N_NODES / 64, HEADS);
    whT_split_kernel<<<gT, 256>>>();

    dim3 gD(N_NODES / RT, HEADS);
    gat_mma_kernel<<<gD, 256>>>(out);
}

// round 5
// speedup vs baseline: 2.3986x; 1.1085x over previous
#include <cuda_runtime.h>
#include <cuda_bf16.h>
#include <cstdint>

#define N_NODES 4096
#define IN_F 512
#define OUT_F 64
#define HEADS 8
#define ALPHA 0.2f

#define RT 128                 // rows per CTA
#define KC 32                  // k (m) per chunk
#define NCH (N_NODES / KC)     // 128 chunks (gat)
#define NCH_W (IN_F / KC)      // 16 chunks (wh)
#define ASTR 40                // padded bf16 row stride (80 B)
#define BSTR 40

// ---- gat dynamic smem offsets (bytes) ----
#define GA_A(buf, prec) ((buf) * 20480 + (prec) * 10240)           // [128][40] bf16
#define GA_B(buf, prec) (40960 + (buf) * 10240 + (prec) * 5120)    // [64][40] bf16
#define GA_DSH 61440
#define GA_SMEM 62464
// ---- wh dynamic smem offsets ----
#define WH_A(buf, prec) ((buf) * 20480 + (prec) * 10240)
#define WH_B(buf, prec) (40960 + (buf) * 10240 + (prec) * 5120)
#define WH_SMEM 61440

// ---------------- scratch (device globals; no allocation) ----------------
__device__ __align__(16) float g_Wh[HEADS * N_NODES * OUT_F];             // 8 MB [h][n][o]
__device__ float g_f1[HEADS * N_NODES];
__device__ float g_f2[HEADS * N_NODES];
__device__ float g_P1[HEADS * N_NODES];
__device__ float g_P2[HEADS * N_NODES];
__device__ float g_Q1[HEADS * N_NODES];
__device__ float g_Q2[HEADS * N_NODES];
__device__ unsigned g_adjbits[N_NODES * (N_NODES / 32)];                  // 2 MB
__device__ __align__(16) __nv_bfloat16 g_WhT_hi[HEADS * OUT_F * N_NODES]; // 4 MB [h][o][m]
__device__ __align__(16) __nv_bfloat16 g_WhT_lo[HEADS * OUT_F * N_NODES];
__device__ __align__(16) __nv_bfloat16 g_x_hi[N_NODES * IN_F];            // 4 MB [n][k]
__device__ __align__(16) __nv_bfloat16 g_x_lo[N_NODES * IN_F];
__device__ __align__(16) __nv_bfloat16 g_WT_hi[HEADS * OUT_F * IN_F];     // 512 KB [h][o][k]
__device__ __align__(16) __nv_bfloat16 g_WT_lo[HEADS * OUT_F * IN_F];

// ---------------- helpers ----------------
__device__ __forceinline__ uint32_t smem_u32(const void* p) {
    uint32_t a;
    asm("{ .reg .u64 t; cvta.to.shared.u64 t, %1; cvt.u32.u64 %0, t; }" : "=r"(a) : "l"(p));
    return a;
}
__device__ __forceinline__ void cp16(uint32_t dst, const void* src) {
    asm volatile("cp.async.cg.shared.global [%0], [%1], 16;" :: "r"(dst), "l"(src) : "memory");
}
__device__ __forceinline__ void cp_commit() {
    asm volatile("cp.async.commit_group;" ::: "memory");
}
template <int N>
__device__ __forceinline__ void cp_wait() {
    asm volatile("cp.async.wait_group %0;" :: "n"(N) : "memory");
}
__device__ __forceinline__ void ldm4(uint32_t* r, uint32_t addr) {
    asm volatile("ldmatrix.sync.aligned.m8n8.x4.shared.b16 {%0,%1,%2,%3}, [%4];"
                 : "=r"(r[0]), "=r"(r[1]), "=r"(r[2]), "=r"(r[3]) : "r"(addr) : "memory");
}
__device__ __forceinline__ void mma_bf16(float* c, const uint32_t* a, uint32_t b0,
                                         uint32_t b1) {
    asm("mma.sync.aligned.m16n8k16.row.col.f32.bf16.bf16.f32 "
        "{%0,%1,%2,%3}, {%4,%5,%6,%7}, {%8,%9}, {%0,%1,%2,%3};"
        : "+f"(c[0]), "+f"(c[1]), "+f"(c[2]), "+f"(c[3])
        : "r"(a[0]), "r"(a[1]), "r"(a[2]), "r"(a[3]), "r"(b0), "r"(b1));
}
__device__ __forceinline__ void split_pair(float x, float y, unsigned& hi, unsigned& lo) {
    __nv_bfloat162 h2 = __float22bfloat162_rn(make_float2(x, y));
    float2 hf = __bfloat1622float2(h2);
    __nv_bfloat162 l2 = __float22bfloat162_rn(make_float2(x - hf.x, y - hf.y));
    hi = *reinterpret_cast<unsigned*>(&h2);
    lo = *reinterpret_cast<unsigned*>(&l2);
}

// ---------------- kernel: bit-pack adjacency ----------------
__global__ void bitpack_kernel(const int* __restrict__ adj) {
    int gid = blockIdx.x * blockDim.x + threadIdx.x;
    unsigned m = __ballot_sync(0xffffffffu, adj[gid] > 0);
    if ((threadIdx.x & 31) == 0) g_adjbits[gid >> 5] = m;
}

// ---------------- kernel: split x into bf16 hi/lo ----------------
__global__ __launch_bounds__(256) void xsplit_kernel(const float* __restrict__ x) {
    int gid = blockIdx.x * blockDim.x + threadIdx.x;   // 262144 threads, 8 floats each
    const float4* xp = (const float4*)x + gid * 2;
    float4 v0 = xp[0], v1 = xp[1];
    float f[8] = {v0.x, v0.y, v0.z, v0.w, v1.x, v1.y, v1.z, v1.w};
    unsigned hw[4], lw[4];
#pragma unroll
    for (int i = 0; i < 4; i++) split_pair(f[2 * i], f[2 * i + 1], hw[i], lw[i]);
    *(uint4*)(g_x_hi + (size_t)gid * 8) = make_uint4(hw[0], hw[1], hw[2], hw[3]);
    *(uint4*)(g_x_lo + (size_t)gid * 8) = make_uint4(lw[0], lw[1], lw[2], lw[3]);
}

// ---------------- kernel: transpose + split W -> WT[h][o][k] ----------------
__global__ __launch_bounds__(256) void wsplit_kernel(const float* __restrict__ W) {
    const int h = blockIdx.x;
    const int t = threadIdx.x;
#pragma unroll 4
    for (int i = 0; i < 128; i++) {
        int lin = i * 256 + t;          // 32768 per head
        int o = lin >> 9, k = lin & 511;
        float v = W[((size_t)h * IN_F + k) * OUT_F + o];
        __nv_bfloat16 hb = __float2bfloat16(v);
        __nv_bfloat16 lb = __float2bfloat16(v - __bfloat162float(hb));
        size_t d = ((size_t)h * OUT_F + o) * IN_F + k;
        g_WT_hi[d] = hb;
        g_WT_lo[d] = lb;
    }
}

// ---------------- kernel: Wh = x @ W via HMMA (3-term bf16 split) ----------------
__global__ __launch_bounds__(256, 2) void wh_mma_kernel() {
    extern __shared__ __align__(16) char sm[];
    const int t = threadIdx.x;
    const int wid = t >> 5, lane = t & 31;
    const int h = blockIdx.y;
    const int nbase = blockIdx.x * RT;

    // A staging: 1024 quads (prec, row, q), 4 per thread
    const int a_p[4] = {(t * 4) >> 9, (t * 4 + 1) >> 9, (t * 4 + 2) >> 9, (t * 4 + 3) >> 9};
    int a_r[4], a_q[4];
    const __nv_bfloat16* a_src[4];
    uint32_t a_doff[4];
#pragma unroll
    for (int i = 0; i < 4; i++) {
        int idx = t * 4 + i;
        a_r[i] = (idx >> 2) & 127;
        a_q[i] = idx & 3;
        a_src[i] = (a_p[i] ? g_x_lo : g_x_hi) + (size_t)(nbase + a_r[i]) * IN_F + a_q[i] * 8;
        a_doff[i] = (uint32_t)(a_r[i] * (ASTR * 2) + a_q[i] * 16);
    }
    // B staging: 512 quads, 2 per thread
    int b_p[2], b_r[2], b_q[2];
    const __nv_bfloat16* b_src[2];
    uint32_t b_doff[2];
#pragma unroll
    for (int i = 0; i < 2; i++) {
        int idx = t * 2 + i;
        b_p[i] = idx >> 8;
        b_r[i] = (idx >> 2) & 63;
        b_q[i] = idx & 3;
        b_src[i] = (b_p[i] ? g_WT_lo : g_WT_hi) + ((size_t)h * OUT_F + b_r[i]) * IN_F +
                   b_q[i] * 8;
        b_doff[i] = (uint32_t)(b_r[i] * (BSTR * 2) + b_q[i] * 16);
    }
    const uint32_t smb = smem_u32(sm);

    // prologue: stage chunk 0 -> buf 0
#pragma unroll
    for (int i = 0; i < 4; i++) cp16(smb + WH_A(0, a_p[i]) + a_doff[i], a_src[i]);
#pragma unroll
    for (int i = 0; i < 2; i++) cp16(smb + WH_B(0, b_p[i]) + b_doff[i], b_src[i]);
    cp_commit();

    float acc[8][4];
#pragma unroll
    for (int j = 0; j < 8; j++)
#pragma unroll
        for (int q = 0; q < 4; q++) acc[j][q] = 0.f;

    const uint32_t aRow = (16 * wid + (lane & 15)) * (ASTR * 2) + (lane >> 4) * 16;
    const uint32_t bRow = (lane & 7) * (BSTR * 2) + (lane >> 3) * 16;

    for (int c = 0; c < NCH_W; c++) {
        const int p = c & 1, pn = p ^ 1;
        cp_wait<0>();
        __syncthreads();
        if (c + 1 < NCH_W) {
            const int kb = (c + 1) * KC;
#pragma unroll
            for (int i = 0; i < 4; i++) cp16(smb + WH_A(pn, a_p[i]) + a_doff[i], a_src[i] + kb);
#pragma unroll
            for (int i = 0; i < 2; i++) cp16(smb + WH_B(pn, b_p[i]) + b_doff[i], b_src[i] + kb);
            cp_commit();
        }
        uint32_t afh[2][4], afl[2][4];
        ldm4(afh[0], smb + WH_A(p, 0) + aRow);
        ldm4(afh[1], smb + WH_A(p, 0) + aRow + 32);
        ldm4(afl[0], smb + WH_A(p, 1) + aRow);
        ldm4(afl[1], smb + WH_A(p, 1) + aRow + 32);
#pragma unroll
        for (int j = 0; j < 8; j++) {
            uint32_t bh[4], bl[4];
            ldm4(bh, smb + WH_B(p, 0) + j * 8 * (BSTR * 2) + bRow);
            ldm4(bl, smb + WH_B(p, 1) + j * 8 * (BSTR * 2) + bRow);
            mma_bf16(acc[j], afh[0], bh[0], bh[1]);
            mma_bf16(acc[j], afh[0], bl[0], bl[1]);
            mma_bf16(acc[j], afl[0], bh[0], bh[1]);
            mma_bf16(acc[j], afh[1], bh[2], bh[3]);
            mma_bf16(acc[j], afh[1], bl[2], bl[3]);
            mma_bf16(acc[j], afl[1], bh[2], bh[3]);
        }
    }

    const int g = lane >> 2;
    const int row0 = nbase + 16 * wid + g;
    float* o0 = g_Wh + ((size_t)h * N_NODES + row0) * OUT_F + (lane & 3) * 2;
    float* o1 = o0 + 8 * OUT_F;
#pragma unroll
    for (int j = 0; j < 8; j++) {
        *(float2*)(o0 + j * 8) = make_float2(acc[j][0], acc[j][1]);
        *(float2*)(o1 + j * 8) = make_float2(acc[j][2], acc[j][3]);
    }
}

// ---------------- kernel: f1/f2 + exp tables ----------------
__global__ void attn_vec_kernel(const float* __restrict__ a1,
                                const float* __restrict__ a2) {
    int gw = (blockIdx.x * blockDim.x + threadIdx.x) >> 5;
    int lane = threadIdx.x & 31;
    if (gw >= HEADS * N_NODES) return;
    int h = gw >> 12;
    int n = gw & (N_NODES - 1);
    const float* whp = &g_Wh[(h * N_NODES + n) * OUT_F];
    float w0 = whp[lane], w1 = whp[lane + 32];
    float s1 = w0 * a1[h * OUT_F + lane] + w1 * a1[h * OUT_F + lane + 32];
    float s2 = w0 * a2[h * OUT_F + lane] + w1 * a2[h * OUT_F + lane + 32];
#pragma unroll
    for (int off = 16; off; off >>= 1) {
        s1 += __shfl_xor_sync(0xffffffffu, s1, off);
        s2 += __shfl_xor_sync(0xffffffffu, s2, off);
    }
    if (lane == 0) {
        int idx = h * N_NODES + n;
        g_f1[idx] = s1;
        g_P1[idx] = expf(s1);
        g_Q1[idx] = expf(ALPHA * s1);
        g_f2[idx] = s2;
        g_P2[idx] = expf(s2);
        g_Q2[idx] = expf(ALPHA * s2);
    }
}

// ---------------- kernel: transpose + bf16 split of Wh ----------------
__global__ __launch_bounds__(256) void whT_split_kernel() {
    __shared__ float T[64 * 65];
    const int h = blockIdx.y;
    const int mb = blockIdx.x * 64;
    const int t = threadIdx.x;
    const float* src = g_Wh + ((size_t)h * N_NODES + mb) * OUT_F;
#pragma unroll
    for (int i = 0; i < 16; i++) {
        int lin = t + i * 256;
        int m = lin >> 6, o = lin & 63;
        T[m * 65 + o] = src[lin];
    }
    __syncthreads();
#pragma unroll
    for (int i = 0; i < 8; i++) {
        int lin = t + i * 256;
        int o = lin >> 5, mp = lin & 31;
        unsigned hw, lw;
        split_pair(T[(2 * mp) * 65 + o], T[(2 * mp + 1) * 65 + o], hw, lw);
        size_t dst = ((size_t)h * OUT_F + o) * N_NODES + mb + 2 * mp;
        *reinterpret_cast<unsigned*>(&g_WhT_hi[dst]) = hw;
        *reinterpret_cast<unsigned*>(&g_WhT_lo[dst]) = lw;
    }
}

// ---------------- kernel: HMMA fused masked-softmax aggregation ----------------
__global__ __launch_bounds__(256, 2) void gat_mma_kernel(float* __restrict__ out) {
    extern __shared__ __align__(16) char sm[];
    const int t = threadIdx.x;
    const int wid = t >> 5, lane = t & 31;
    const int h = blockIdx.y;
    const int nbase = blockIdx.x * RT;
    const int hN = h * N_NODES;
    const uint32_t smb = smem_u32(sm);

    const int r = t >> 1;
    const int half = t & 1;
    const int grow = nbase + r;
    const float F1r = g_f1[hN + grow];
    const float P1r = g_P1[hN + grow];
    const float Q1r = g_Q1[hN + grow];
    const unsigned* adjrow = g_adjbits + (size_t)grow * (N_NODES / 32);
    float Dacc = 0.f;

    const __nv_bfloat16* whTh = g_WhT_hi + ((size_t)h * OUT_F) * N_NODES;
    const __nv_bfloat16* whTl = g_WhT_lo + ((size_t)h * OUT_F) * N_NODES;

    // B staging: 512 quads, 2 per thread
    int b_p[2], b_r[2], b_q[2];
    const __nv_bfloat16* b_src[2];
    uint32_t b_doff[2];
#pragma unroll
    for (int i = 0; i < 2; i++) {
        int idx = t * 2 + i;
        b_p[i] = idx >> 8;
        b_r[i] = (idx >> 2) & 63;
        b_q[i] = idx & 3;
        b_src[i] = (b_p[i] ? whTl : whTh) + (size_t)b_r[i] * N_NODES + b_q[i] * 8;
        b_doff[i] = (uint32_t)(b_r[i] * (BSTR * 2) + b_q[i] * 16);
    }

    // w-gen for chunk cn into A buffer `buf`
    auto wgen = [&](int cn, int buf) {
        const int mb = cn * KC + half * 16;
        const unsigned aw = adjrow[cn];
        const uint32_t dhA = smb + GA_A(buf, 0) + r * (ASTR * 2) + (half * 16) * 2;
        const uint32_t dlA = smb + GA_A(buf, 1) + r * (ASTR * 2) + (half * 16) * 2;
#pragma unroll
        for (int q = 0; q < 4; q++) {
            float4 f2v = *(const float4*)(g_f2 + hN + mb + q * 4);
            float4 p2v = *(const float4*)(g_P2 + hN + mb + q * 4);
            float4 q2v = *(const float4*)(g_Q2 + hN + mb + q * 4);
            float fv[4] = {f2v.x, f2v.y, f2v.z, f2v.w};
            float pv[4] = {p2v.x, p2v.y, p2v.z, p2v.w};
            float qv[4] = {q2v.x, q2v.y, q2v.z, q2v.w};
            float wv[4];
#pragma unroll
            for (int e = 0; e < 4; e++) {
                int bit = half * 16 + q * 4 + e;
                float pos = F1r + fv[e];
                float w = (pos > 0.f) ? (P1r * pv[e]) : (Q1r * qv[e]);
                w = ((aw >> bit) & 1u) ? w : 0.f;
                Dacc += w;
                wv[e] = w;
            }
            unsigned h0, l0, h1, l1;
            split_pair(wv[0], wv[1], h0, l0);
            split_pair(wv[2], wv[3], h1, l1);
            asm volatile("st.shared.v2.b32 [%0], {%1, %2};" :: "r"(dhA + q * 8), "r"(h0),
                         "r"(h1) : "memory");
            asm volatile("st.shared.v2.b32 [%0], {%1, %2};" :: "r"(dlA + q * 8), "r"(l0),
                         "r"(l1) : "memory");
        }
    };

    // prologue: B(0) + A(0) -> buf 0
#pragma unroll
    for (int i = 0; i < 2; i++) cp16(smb + GA_B(0, b_p[i]) + b_doff[i], b_src[i]);
    cp_commit();
    wgen(0, 0);
    cp_wait<0>();
    __syncthreads();

    float acc[8][4];
#pragma unroll
    for (int j = 0; j < 8; j++)
#pragma unroll
        for (int q = 0; q < 4; q++) acc[j][q] = 0.f;

    const uint32_t aRow = (16 * wid + (lane & 15)) * (ASTR * 2) + (lane >> 4) * 16;
    const uint32_t bRow = (lane & 7) * (BSTR * 2) + (lane >> 3) * 16;

    for (int c = 0; c < NCH; c++) {
        const int p = c & 1, pn = p ^ 1;
        // stage next B (goes to other buffer)
        if (c + 1 < NCH) {
            const int mb2 = (c + 1) * KC;
#pragma unroll
            for (int i = 0; i < 2; i++)
                cp16(smb + GA_B(pn, b_p[i]) + b_doff[i], b_src[i] + mb2);
            cp_commit();
        }
        // MMA on chunk c (buffer p) — issue first so tensor pipe is fed
        uint32_t afh[2][4], afl[2][4];
        ldm4(afh[0], smb + GA_A(p, 0) + aRow);
        ldm4(afh[1], smb + GA_A(p, 0) + aRow + 32);
        ldm4(afl[0], smb + GA_A(p, 1) + aRow);
        ldm4(afl[1], smb + GA_A(p, 1) + aRow + 32);
#pragma unroll
        for (int j = 0; j < 8; j++) {
            uint32_t bh[4], bl[4];
            ldm4(bh, smb + GA_B(p, 0) + j * 8 * (BSTR * 2) + bRow);
            ldm4(bl, smb + GA_B(p, 1) + j * 8 * (BSTR * 2) + bRow);
            mma_bf16(acc[j], afh[0], bh[0], bh[1]);
            mma_bf16(acc[j], afh[0], bl[0], bl[1]);
            mma_bf16(acc[j], afl[0], bh[0], bh[1]);
            mma_bf16(acc[j], afh[1], bh[2], bh[3]);
            mma_bf16(acc[j], afh[1], bl[2], bl[3]);
            mma_bf16(acc[j], afl[1], bh[2], bh[3]);
        }
        // w-gen for next chunk into other A buffer (overlaps MMA execution)
        if (c + 1 < NCH) {
            wgen(c + 1, pn);
            cp_wait<0>();
        }
        __syncthreads();
    }

    float* Dsh = (float*)(sm + GA_DSH);
    Dsh[t] = Dacc;
    __syncthreads();

    const int g = lane >> 2;
    const int row0 = 16 * wid + g;
    const int row1 = row0 + 8;
    const float inv0 = 1.0f / (Dsh[2 * row0] + Dsh[2 * row0 + 1]);
    const float inv1 = 1.0f / (Dsh[2 * row1] + Dsh[2 * row1 + 1]);
    float* o0 = out + (size_t)(nbase + row0) * (HEADS * OUT_F) + h * OUT_F + (lane & 3) * 2;
    float* o1 = out + (size_t)(nbase + row1) * (HEADS * OUT_F) + h * OUT_F + (lane & 3) * 2;
#pragma unroll
    for (int j = 0; j < 8; j++) {
        *(float2*)(o0 + j * 8) = make_float2(acc[j][0] * inv0, acc[j][1] * inv0);
        *(float2*)(o1 + j * 8) = make_float2(acc[j][2] * inv1, acc[j][3] * inv1);
    }
}

// ---------------- launch ----------------
extern "C" void kernel_launch(void* const* d_in, const int* in_sizes, int n_in,
                              void* d_out, int out_size) {
    const float* x   = (const float*)d_in[0];
    const int*   adj = (const int*)d_in[1];
    const float* W   = (const float*)d_in[2];
    const float* a1  = (const float*)d_in[3];
    const float* a2  = (const float*)d_in[4];
    float* out = (float*)d_out;

    cudaFuncSetAttribute(wh_mma_kernel, cudaFuncAttributeMaxDynamicSharedMemorySize,
                         WH_SMEM);
    cudaFuncSetAttribute(gat_mma_kernel, cudaFuncAttributeMaxDynamicSharedMemorySize,
                         GA_SMEM);

    bitpack_kernel<<<(N_NODES * N_NODES) / 256, 256>>>(adj);
    xsplit_kernel<<<(N_NODES * IN_F) / (256 * 8), 256>>>(x);
    wsplit_kernel<<<HEADS, 256>>>(W);

    dim3 gW(N_NODES / RT, HEADS);
    wh_mma_kernel<<<gW, 256, WH_SMEM>>>();

    attn_vec_kernel<<<(HEADS * N_NODES * 32) / 256, 256>>>(a1, a2);

    dim3 gT(N_NODES / 64, HEADS);
    whT_split_kernel<<<gT, 256>>>();

    dim3 gD(N_NODES / RT, HEADS);
    gat_mma_kernel<<<gD, 256, GA_SMEM>>>(out);
}

// round 6
// speedup vs baseline: 2.5621x; 1.0681x over previous
#include <cuda_runtime.h>
#include <cuda_bf16.h>
#include <cuda_fp16.h>
#include <cstdint>

#define N_NODES 4096
#define IN_F 512
#define OUT_F 64
#define HEADS 8
#define ALPHA 0.2f

#define RT 128                 // rows per CTA (wh kernel)
#define KC 32                  // k (m) per chunk
#define NCH (N_NODES / KC)     // 128 chunks (gat)
#define NCH_W (IN_F / KC)      // 16 chunks (wh)
#define ASTR 40                // padded bf16/fp16 row stride (80 B)
#define BSTR 40

// ---- wh dynamic smem offsets ----
#define WH_A(buf, prec) ((buf) * 20480 + (prec) * 10240)
#define WH_B(buf, prec) (40960 + (buf) * 10240 + (prec) * 5120)
#define WH_SMEM 61440
// ---- gat (fp16, RT=64) smem offsets ----
#define GA_A(buf)       ((buf) * 5120)                             // [64][40] fp16
#define GA_B(buf, prec) (10240 + (buf) * 10240 + (prec) * 5120)    // [64][40] fp16
#define GA_DSH 30720
#define GA_SMEM 31744
#define GAT_RT 64

// ---------------- scratch (device globals; no allocation) ----------------
__device__ __align__(16) float g_Wh[HEADS * N_NODES * OUT_F];          // 8 MB [h][n][o]
__device__ float g_f1[HEADS * N_NODES];
__device__ float g_f2[HEADS * N_NODES];
__device__ float g_P1[HEADS * N_NODES];   // exp(f1 - M)  (shifted)
__device__ float g_P2[HEADS * N_NODES];   // exp(f2)
__device__ float g_Q1[HEADS * N_NODES];   // exp(a*f1 - M)
__device__ float g_Q2[HEADS * N_NODES];   // exp(a*f2)
__device__ float g_mx[HEADS];             // per-head max f2
__device__ unsigned g_adjbits[N_NODES * (N_NODES / 32)];               // 2 MB
__device__ __align__(16) __half g_WhT_h16[HEADS * OUT_F * N_NODES];    // 4 MB [h][o][m]
__device__ __align__(16) __half g_WhT_l16[HEADS * OUT_F * N_NODES];
__device__ __align__(16) __nv_bfloat16 g_x_hi[N_NODES * IN_F];         // 4 MB [n][k]
__device__ __align__(16) __nv_bfloat16 g_x_lo[N_NODES * IN_F];
__device__ __align__(16) __nv_bfloat16 g_WT_hi[HEADS * OUT_F * IN_F];  // 512 KB [h][o][k]
__device__ __align__(16) __nv_bfloat16 g_WT_lo[HEADS * OUT_F * IN_F];

// ---------------- helpers ----------------
__device__ __forceinline__ uint32_t smem_u32(const void* p) {
    uint32_t a;
    asm("{ .reg .u64 t; cvta.to.shared.u64 t, %1; cvt.u32.u64 %0, t; }" : "=r"(a) : "l"(p));
    return a;
}
__device__ __forceinline__ void cp16(uint32_t dst, const void* src) {
    asm volatile("cp.async.cg.shared.global [%0], [%1], 16;" :: "r"(dst), "l"(src) : "memory");
}
__device__ __forceinline__ void cp_commit() {
    asm volatile("cp.async.commit_group;" ::: "memory");
}
template <int N>
__device__ __forceinline__ void cp_wait() {
    asm volatile("cp.async.wait_group %0;" :: "n"(N) : "memory");
}
__device__ __forceinline__ void ldm4(uint32_t* r, uint32_t addr) {
    asm volatile("ldmatrix.sync.aligned.m8n8.x4.shared.b16 {%0,%1,%2,%3}, [%4];"
                 : "=r"(r[0]), "=r"(r[1]), "=r"(r[2]), "=r"(r[3]) : "r"(addr) : "memory");
}
__device__ __forceinline__ void mma_bf16(float* c, const uint32_t* a, uint32_t b0,
                                         uint32_t b1) {
    asm("mma.sync.aligned.m16n8k16.row.col.f32.bf16.bf16.f32 "
        "{%0,%1,%2,%3}, {%4,%5,%6,%7}, {%8,%9}, {%0,%1,%2,%3};"
        : "+f"(c[0]), "+f"(c[1]), "+f"(c[2]), "+f"(c[3])
        : "r"(a[0]), "r"(a[1]), "r"(a[2]), "r"(a[3]), "r"(b0), "r"(b1));
}
__device__ __forceinline__ void mma_f16(float* c, const uint32_t* a, uint32_t b0,
                                        uint32_t b1) {
    asm("mma.sync.aligned.m16n8k16.row.col.f32.f16.f16.f32 "
        "{%0,%1,%2,%3}, {%4,%5,%6,%7}, {%8,%9}, {%0,%1,%2,%3};"
        : "+f"(c[0]), "+f"(c[1]), "+f"(c[2]), "+f"(c[3])
        : "r"(a[0]), "r"(a[1]), "r"(a[2]), "r"(a[3]), "r"(b0), "r"(b1));
}
__device__ __forceinline__ void split_pair(float x, float y, unsigned& hi, unsigned& lo) {
    __nv_bfloat162 h2 = __float22bfloat162_rn(make_float2(x, y));
    float2 hf = __bfloat1622float2(h2);
    __nv_bfloat162 l2 = __float22bfloat162_rn(make_float2(x - hf.x, y - hf.y));
    hi = *reinterpret_cast<unsigned*>(&h2);
    lo = *reinterpret_cast<unsigned*>(&l2);
}
__device__ __forceinline__ void split_pair_h(float x, float y, unsigned& hi, unsigned& lo) {
    __half2 h2 = __floats2half2_rn(x, y);
    float2 hf = __half22float2(h2);
    __half2 l2 = __floats2half2_rn(x - hf.x, y - hf.y);
    hi = *reinterpret_cast<unsigned*>(&h2);
    lo = *reinterpret_cast<unsigned*>(&l2);
}

// ---------------- kernel: bit-pack adjacency (32 entries / thread) ----------------
__global__ __launch_bounds__(256) void bitpack_kernel(const int* __restrict__ adj) {
    int t = blockIdx.x * blockDim.x + threadIdx.x;       // 524288 threads
    const int4* p = (const int4*)adj + (size_t)t * 8;
    unsigned w = 0;
#pragma unroll
    for (int i = 0; i < 8; i++) {
        int4 v = p[i];
        w |= (v.x > 0 ? 1u : 0u) << (4 * i);
        w |= (v.y > 0 ? 1u : 0u) << (4 * i + 1);
        w |= (v.z > 0 ? 1u : 0u) << (4 * i + 2);
        w |= (v.w > 0 ? 1u : 0u) << (4 * i + 3);
    }
    g_adjbits[t] = w;
}

// ---------------- kernel: split x into bf16 hi/lo ----------------
__global__ __launch_bounds__(256) void xsplit_kernel(const float* __restrict__ x) {
    int gid = blockIdx.x * blockDim.x + threadIdx.x;
    const float4* xp = (const float4*)x + gid * 2;
    float4 v0 = xp[0], v1 = xp[1];
    float f[8] = {v0.x, v0.y, v0.z, v0.w, v1.x, v1.y, v1.z, v1.w};
    unsigned hw[4], lw[4];
#pragma unroll
    for (int i = 0; i < 4; i++) split_pair(f[2 * i], f[2 * i + 1], hw[i], lw[i]);
    *(uint4*)(g_x_hi + (size_t)gid * 8) = make_uint4(hw[0], hw[1], hw[2], hw[3]);
    *(uint4*)(g_x_lo + (size_t)gid * 8) = make_uint4(lw[0], lw[1], lw[2], lw[3]);
}

// ---------------- kernel: transpose + split W -> WT[h][o][k] ----------------
__global__ __launch_bounds__(256) void wsplit_kernel(const float* __restrict__ W) {
    const int h = blockIdx.x;
    const int t = threadIdx.x;
#pragma unroll 4
    for (int i = 0; i < 128; i++) {
        int lin = i * 256 + t;
        int o = lin >> 9, k = lin & 511;
        float v = W[((size_t)h * IN_F + k) * OUT_F + o];
        __nv_bfloat16 hb = __float2bfloat16(v);
        __nv_bfloat16 lb = __float2bfloat16(v - __bfloat162float(hb));
        size_t d = ((size_t)h * OUT_F + o) * IN_F + k;
        g_WT_hi[d] = hb;
        g_WT_lo[d] = lb;
    }
}

// ---------------- kernel: Wh = x @ W via HMMA (3-term bf16 split) ----------------
__global__ __launch_bounds__(256, 2) void wh_mma_kernel() {
    extern __shared__ __align__(16) char sm[];
    const int t = threadIdx.x;
    const int wid = t >> 5, lane = t & 31;
    const int h = blockIdx.y;
    const int nbase = blockIdx.x * RT;

    const int a_p[4] = {(t * 4) >> 9, (t * 4 + 1) >> 9, (t * 4 + 2) >> 9, (t * 4 + 3) >> 9};
    int a_r[4], a_q[4];
    const __nv_bfloat16* a_src[4];
    uint32_t a_doff[4];
#pragma unroll
    for (int i = 0; i < 4; i++) {
        int idx = t * 4 + i;
        a_r[i] = (idx >> 2) & 127;
        a_q[i] = idx & 3;
        a_src[i] = (a_p[i] ? g_x_lo : g_x_hi) + (size_t)(nbase + a_r[i]) * IN_F + a_q[i] * 8;
        a_doff[i] = (uint32_t)(a_r[i] * (ASTR * 2) + a_q[i] * 16);
    }
    int b_p[2], b_r[2], b_q[2];
    const __nv_bfloat16* b_src[2];
    uint32_t b_doff[2];
#pragma unroll
    for (int i = 0; i < 2; i++) {
        int idx = t * 2 + i;
        b_p[i] = idx >> 8;
        b_r[i] = (idx >> 2) & 63;
        b_q[i] = idx & 3;
        b_src[i] = (b_p[i] ? g_WT_lo : g_WT_hi) + ((size_t)h * OUT_F + b_r[i]) * IN_F +
                   b_q[i] * 8;
        b_doff[i] = (uint32_t)(b_r[i] * (BSTR * 2) + b_q[i] * 16);
    }
    const uint32_t smb = smem_u32(sm);

#pragma unroll
    for (int i = 0; i < 4; i++) cp16(smb + WH_A(0, a_p[i]) + a_doff[i], a_src[i]);
#pragma unroll
    for (int i = 0; i < 2; i++) cp16(smb + WH_B(0, b_p[i]) + b_doff[i], b_src[i]);
    cp_commit();

    float acc[8][4];
#pragma unroll
    for (int j = 0; j < 8; j++)
#pragma unroll
        for (int q = 0; q < 4; q++) acc[j][q] = 0.f;

    const uint32_t aRow = (16 * wid + (lane & 15)) * (ASTR * 2) + (lane >> 4) * 16;
    const uint32_t bRow = (lane & 7) * (BSTR * 2) + (lane >> 3) * 16;

    for (int c = 0; c < NCH_W; c++) {
        const int p = c & 1, pn = p ^ 1;
        cp_wait<0>();
        __syncthreads();
        if (c + 1 < NCH_W) {
            const int kb = (c + 1) * KC;
#pragma unroll
            for (int i = 0; i < 4; i++) cp16(smb + WH_A(pn, a_p[i]) + a_doff[i], a_src[i] + kb);
#pragma unroll
            for (int i = 0; i < 2; i++) cp16(smb + WH_B(pn, b_p[i]) + b_doff[i], b_src[i] + kb);
            cp_commit();
        }
        uint32_t afh[2][4], afl[2][4];
        ldm4(afh[0], smb + WH_A(p, 0) + aRow);
        ldm4(afh[1], smb + WH_A(p, 0) + aRow + 32);
        ldm4(afl[0], smb + WH_A(p, 1) + aRow);
        ldm4(afl[1], smb + WH_A(p, 1) + aRow + 32);
#pragma unroll
        for (int j = 0; j < 8; j++) {
            uint32_t bh[4], bl[4];
            ldm4(bh, smb + WH_B(p, 0) + j * 8 * (BSTR * 2) + bRow);
            ldm4(bl, smb + WH_B(p, 1) + j * 8 * (BSTR * 2) + bRow);
            mma_bf16(acc[j], afh[0], bh[0], bh[1]);
            mma_bf16(acc[j], afh[0], bl[0], bl[1]);
            mma_bf16(acc[j], afl[0], bh[0], bh[1]);
            mma_bf16(acc[j], afh[1], bh[2], bh[3]);
            mma_bf16(acc[j], afh[1], bl[2], bl[3]);
            mma_bf16(acc[j], afl[1], bh[2], bh[3]);
        }
    }

    const int g = lane >> 2;
    const int row0 = nbase + 16 * wid + g;
    float* o0 = g_Wh + ((size_t)h * N_NODES + row0) * OUT_F + (lane & 3) * 2;
    float* o1 = o0 + 8 * OUT_F;
#pragma unroll
    for (int j = 0; j < 8; j++) {
        *(float2*)(o0 + j * 8) = make_float2(acc[j][0], acc[j][1]);
        *(float2*)(o1 + j * 8) = make_float2(acc[j][2], acc[j][3]);
    }
}

// ---------------- kernel: f1/f2 + unshifted exp tables ----------------
__global__ void attn_vec_kernel(const float* __restrict__ a1,
                                const float* __restrict__ a2) {
    int gw = (blockIdx.x * blockDim.x + threadIdx.x) >> 5;
    int lane = threadIdx.x & 31;
    if (gw >= HEADS * N_NODES) return;
    int h = gw >> 12;
    int n = gw & (N_NODES - 1);
    const float* whp = &g_Wh[(h * N_NODES + n) * OUT_F];
    float w0 = whp[lane], w1 = whp[lane + 32];
    float s1 = w0 * a1[h * OUT_F + lane] + w1 * a1[h * OUT_F + lane + 32];
    float s2 = w0 * a2[h * OUT_F + lane] + w1 * a2[h * OUT_F + lane + 32];
#pragma unroll
    for (int off = 16; off; off >>= 1) {
        s1 += __shfl_xor_sync(0xffffffffu, s1, off);
        s2 += __shfl_xor_sync(0xffffffffu, s2, off);
    }
    if (lane == 0) {
        int idx = h * N_NODES + n;
        g_f1[idx] = s1;
        g_f2[idx] = s2;
        g_P2[idx] = expf(s2);
        g_Q2[idx] = expf(ALPHA * s2);
    }
}

// ---------------- kernel: per-head max of f2 ----------------
__global__ __launch_bounds__(256) void maxf2_kernel() {
    __shared__ float red[256];
    const int h = blockIdx.x, t = threadIdx.x;
    float m = -3.4e38f;
#pragma unroll
    for (int i = 0; i < 16; i++) m = fmaxf(m, g_f2[h * N_NODES + t + i * 256]);
    red[t] = m;
    __syncthreads();
    for (int s = 128; s; s >>= 1) {
        if (t < s) red[t] = fmaxf(red[t], red[t + s]);
        __syncthreads();
    }
    if (t == 0) g_mx[h] = red[0];
}

// ---------------- kernel: shifted P1/Q1 ----------------
__global__ __launch_bounds__(256) void exp1_kernel() {
    int idx = blockIdx.x * blockDim.x + threadIdx.x;    // HEADS*N
    int h = idx >> 12;
    float f1 = g_f1[idx];
    float s = f1 + g_mx[h];
    float M = s > 0.f ? s : ALPHA * s;                  // row max of leakyrelu logits
    g_P1[idx] = expf(f1 - M);
    g_Q1[idx] = expf(ALPHA * f1 - M);
}

// ---------------- kernel: transpose + fp16 split of Wh ----------------
__global__ __launch_bounds__(256) void whT_split_kernel() {
    __shared__ float T[64 * 65];
    const int h = blockIdx.y;
    const int mb = blockIdx.x * 64;
    const int t = threadIdx.x;
    const float* src = g_Wh + ((size_t)h * N_NODES + mb) * OUT_F;
#pragma unroll
    for (int i = 0; i < 16; i++) {
        int lin = t + i * 256;
        int m = lin >> 6, o = lin & 63;
        T[m * 65 + o] = src[lin];
    }
    __syncthreads();
#pragma unroll
    for (int i = 0; i < 8; i++) {
        int lin = t + i * 256;
        int o = lin >> 5, mp = lin & 31;
        unsigned hw, lw;
        split_pair_h(T[(2 * mp) * 65 + o], T[(2 * mp + 1) * 65 + o], hw, lw);
        size_t dst = ((size_t)h * OUT_F + o) * N_NODES + mb + 2 * mp;
        *reinterpret_cast<unsigned*>(&g_WhT_h16[dst]) = hw;
        *reinterpret_cast<unsigned*>(&g_WhT_l16[dst]) = lw;
    }
}

// ---------------- kernel: fp16 HMMA fused masked-softmax aggregation ----------------
// 64 rows x 64 cols per CTA; 8 warps each 16 rows x 32 cols; 4 MMAs per j.
__global__ __launch_bounds__(256, 3) void gat_mma_kernel(float* __restrict__ out) {
    extern __shared__ __align__(16) char sm[];
    const int t = threadIdx.x;
    const int wid = t >> 5, lane = t & 31;
    const int h = blockIdx.y;
    const int nbase = blockIdx.x * GAT_RT;
    const int hN = h * N_NODES;
    const uint32_t smb = smem_u32(sm);

    // w-gen assignment: row rr (0..63), m-quarter q (8 m's)
    const int rr = t >> 2;
    const int q = t & 3;
    const int grow = nbase + rr;
    const float F1r = g_f1[hN + grow];
    const float P1r = g_P1[hN + grow];
    const float Q1r = g_Q1[hN + grow];
    const unsigned* adjrow = g_adjbits + (size_t)grow * (N_NODES / 32);
    float Dacc = 0.f;

    const __half* whTh = g_WhT_h16 + ((size_t)h * OUT_F) * N_NODES;
    const __half* whTl = g_WhT_l16 + ((size_t)h * OUT_F) * N_NODES;

    // B staging: 512 quads (prec, o-row, 16B quad), 2 per thread
    int b_p[2];
    const __half* b_src[2];
    uint32_t b_doff[2];
#pragma unroll
    for (int i = 0; i < 2; i++) {
        int idx = t * 2 + i;
        b_p[i] = idx >> 8;
        int br = (idx >> 2) & 63, bq = idx & 3;
        b_src[i] = (b_p[i] ? whTl : whTh) + (size_t)br * N_NODES + bq * 8;
        b_doff[i] = (uint32_t)(br * (BSTR * 2) + bq * 16);
    }

    // w-gen chunk cn -> A buffer buf (8 fp16 weights per thread)
    auto wgen = [&](int cn, int buf) {
        const int mb = cn * KC + q * 8;
        const unsigned aw = adjrow[cn];
        float4 f2a = *(const float4*)(g_f2 + hN + mb);
        float4 f2b = *(const float4*)(g_f2 + hN + mb + 4);
        float4 p2a = *(const float4*)(g_P2 + hN + mb);
        float4 p2b = *(const float4*)(g_P2 + hN + mb + 4);
        float4 q2a = *(const float4*)(g_Q2 + hN + mb);
        float4 q2b = *(const float4*)(g_Q2 + hN + mb + 4);
        float fv[8] = {f2a.x, f2a.y, f2a.z, f2a.w, f2b.x, f2b.y, f2b.z, f2b.w};
        float pv[8] = {p2a.x, p2a.y, p2a.z, p2a.w, p2b.x, p2b.y, p2b.z, p2b.w};
        float qv[8] = {q2a.x, q2a.y, q2a.z, q2a.w, q2b.x, q2b.y, q2b.z, q2b.w};
        float wv[8];
#pragma unroll
        for (int e = 0; e < 8; e++) {
            int bit = q * 8 + e;
            float pos = F1r + fv[e];
            float w = (pos > 0.f) ? (P1r * pv[e]) : (Q1r * qv[e]);
            w = ((aw >> bit) & 1u) ? w : 0.f;
            Dacc += w;
            wv[e] = w;
        }
        unsigned hp[4];
#pragma unroll
        for (int e = 0; e < 4; e++) {
            __half2 h2 = __floats2half2_rn(wv[2 * e], wv[2 * e + 1]);
            hp[e] = *reinterpret_cast<unsigned*>(&h2);
        }
        asm volatile("st.shared.v4.b32 [%0], {%1, %2, %3, %4};"
                     :: "r"(smb + GA_A(buf) + rr * (ASTR * 2) + q * 16),
                        "r"(hp[0]), "r"(hp[1]), "r"(hp[2]), "r"(hp[3]) : "memory");
    };

    // prologue
#pragma unroll
    for (int i = 0; i < 2; i++) cp16(smb + GA_B(0, b_p[i]) + b_doff[i], b_src[i]);
    cp_commit();
    wgen(0, 0);
    cp_wait<0>();
    __syncthreads();

    float acc[4][4];
#pragma unroll
    for (int j = 0; j < 4; j++)
#pragma unroll
        for (int e = 0; e < 4; e++) acc[j][e] = 0.f;

    const uint32_t aRow = (16 * (wid & 3) + (lane & 15)) * (ASTR * 2) + (lane >> 4) * 16;
    const int jbase = (wid >> 2) * 32;   // output-column base (o rows of B)
    const uint32_t bOff = (jbase + (lane & 7)) * (BSTR * 2) + (lane >> 3) * 16;

    for (int c = 0; c < NCH; c++) {
        const int p = c & 1, pn = p ^ 1;
        if (c + 1 < NCH) {
            const int mb2 = (c + 1) * KC;
#pragma unroll
            for (int i = 0; i < 2; i++)
                cp16(smb + GA_B(pn, b_p[i]) + b_doff[i], b_src[i] + mb2);
            cp_commit();
        }
        uint32_t af[2][4];
        ldm4(af[0], smb + GA_A(p) + aRow);
        ldm4(af[1], smb + GA_A(p) + aRow + 32);
#pragma unroll
        for (int j = 0; j < 4; j++) {
            uint32_t bh[4], bl[4];
            ldm4(bh, smb + GA_B(p, 0) + j * 8 * (BSTR * 2) + bOff);
            ldm4(bl, smb + GA_B(p, 1) + j * 8 * (BSTR * 2) + bOff);
            mma_f16(acc[j], af[0], bh[0], bh[1]);
            mma_f16(acc[j], af[0], bl[0], bl[1]);
            mma_f16(acc[j], af[1], bh[2], bh[3]);
            mma_f16(acc[j], af[1], bl[2], bl[3]);
        }
        if (c + 1 < NCH) wgen(c + 1, pn);
        cp_wait<0>();
        __syncthreads();
    }

    float* Dsh = (float*)(sm + GA_DSH);
    Dsh[t] = Dacc;
    __syncthreads();

    const int g = lane >> 2;
    const int row0 = 16 * (wid & 3) + g;
    const int row1 = row0 + 8;
    const float inv0 =
        1.0f / (Dsh[4 * row0] + Dsh[4 * row0 + 1] + Dsh[4 * row0 + 2] + Dsh[4 * row0 + 3]);
    const float inv1 =
        1.0f / (Dsh[4 * row1] + Dsh[4 * row1 + 1] + Dsh[4 * row1 + 2] + Dsh[4 * row1 + 3]);
    float* o0 = out + (size_t)(nbase + row0) * (HEADS * OUT_F) + h * OUT_F + jbase +
                (lane & 3) * 2;
    float* o1 = out + (size_t)(nbase + row1) * (HEADS * OUT_F) + h * OUT_F + jbase +
                (lane & 3) * 2;
#pragma unroll
    for (int j = 0; j < 4; j++) {
        *(float2*)(o0 + j * 8) = make_float2(acc[j][0] * inv0, acc[j][1] * inv0);
        *(float2*)(o1 + j * 8) = make_float2(acc[j][2] * inv1, acc[j][3] * inv1);
    }
}

// ---------------- launch ----------------
extern "C" void kernel_launch(void* const* d_in, const int* in_sizes, int n_in,
                              void* d_out, int out_size) {
    const float* x   = (const float*)d_in[0];
    const int*   adj = (const int*)d_in[1];
    const float* W   = (const float*)d_in[2];
    const float* a1  = (const float*)d_in[3];
    const float* a2  = (const float*)d_in[4];
    float* out = (float*)d_out;

    cudaFuncSetAttribute(wh_mma_kernel, cudaFuncAttributeMaxDynamicSharedMemorySize,
                         WH_SMEM);
    cudaFuncSetAttribute(gat_mma_kernel, cudaFuncAttributeMaxDynamicSharedMemorySize,
                         GA_SMEM);

    bitpack_kernel<<<(N_NODES * N_NODES / 32) / 256, 256>>>(adj);
    xsplit_kernel<<<(N_NODES * IN_F) / (256 * 8), 256>>>(x);
    wsplit_kernel<<<HEADS, 256>>>(W);

    dim3 gW(N_NODES / RT, HEADS);
    wh_mma_kernel<<<gW, 256, WH_SMEM>>>();

    attn_vec_kernel<<<(HEADS * N_NODES * 32) / 256, 256>>>(a1, a2);
    maxf2_kernel<<<HEADS, 256>>>();
    exp1_kernel<<<(HEADS * N_NODES) / 256, 256>>>();

    dim3 gT(N_NODES / 64, HEADS);
    whT_split_kernel<<<gT, 256>>>();

    dim3 gD(N_NODES / GAT_RT, HEADS);
    gat_mma_kernel<<<gD, 256, GA_SMEM>>>(out);
}

// round 7
// speedup vs baseline: 3.1476x; 1.2285x over previous
#include <cuda_runtime.h>
#include <cuda_bf16.h>
#include <cuda_fp16.h>
#include <cstdint>

#define N_NODES 4096
#define IN_F 512
#define OUT_F 64
#define HEADS 8
#define ALPHA 0.2f

#define RT 128                 // rows per CTA (wh kernel)
#define KC 32                  // k per chunk (wh kernel)
#define NCH_W (IN_F / KC)      // 16 chunks (wh)
#define ASTR 40                // padded bf16 row stride (80 B) (wh kernel)
#define BSTR 40

// ---- wh dynamic smem offsets ----
#define WH_A(buf, prec) ((buf) * 20480 + (prec) * 10240)
#define WH_B(buf, prec) (40960 + (buf) * 10240 + (prec) * 5120)
#define WH_SMEM 61440

// ---- gat (fp16 single-B, KC=64, RT=64) ----
#define GAT_RT 64
#define KC2 64
#define NCH2 (N_NODES / KC2)   // 64 chunks
#define AST2 72                // fp16 stride (144 B)
#define GA_A(buf) ((buf) * 9216)            // [64][72] fp16
#define GA_B(buf) (18432 + (buf) * 9216)    // [64][72] fp16
#define GA_DSH 36864
#define GA_SMEM 37888

// ---------------- scratch (device globals; no allocation) ----------------
__device__ __align__(16) float g_Wh[HEADS * N_NODES * OUT_F];          // 8 MB [h][n][o]
__device__ float g_f1[HEADS * N_NODES];
__device__ float g_f2[HEADS * N_NODES];
__device__ float g_P1[HEADS * N_NODES];   // exp(f1 - M)  (shifted)
__device__ float g_P2[HEADS * N_NODES];   // exp(f2)
__device__ float g_Q1[HEADS * N_NODES];   // exp(a*f1 - M)
__device__ float g_Q2[HEADS * N_NODES];   // exp(a*f2)
__device__ float g_mx[HEADS];             // per-head max f2
__device__ unsigned g_adjbits[N_NODES * (N_NODES / 32)];               // 2 MB
__device__ __align__(16) __half g_WhT_h16[HEADS * OUT_F * N_NODES];    // 4 MB [h][o][m]
__device__ __align__(16) __nv_bfloat16 g_x_hi[N_NODES * IN_F];         // 4 MB [n][k]
__device__ __align__(16) __nv_bfloat16 g_x_lo[N_NODES * IN_F];
__device__ __align__(16) __nv_bfloat16 g_WT_hi[HEADS * OUT_F * IN_F];  // 512 KB [h][o][k]
__device__ __align__(16) __nv_bfloat16 g_WT_lo[HEADS * OUT_F * IN_F];

// ---------------- helpers ----------------
__device__ __forceinline__ uint32_t smem_u32(const void* p) {
    uint32_t a;
    asm("{ .reg .u64 t; cvta.to.shared.u64 t, %1; cvt.u32.u64 %0, t; }" : "=r"(a) : "l"(p));
    return a;
}
__device__ __forceinline__ void cp16(uint32_t dst, const void* src) {
    asm volatile("cp.async.cg.shared.global [%0], [%1], 16;" :: "r"(dst), "l"(src) : "memory");
}
__device__ __forceinline__ void cp_commit() {
    asm volatile("cp.async.commit_group;" ::: "memory");
}
template <int N>
__device__ __forceinline__ void cp_wait() {
    asm volatile("cp.async.wait_group %0;" :: "n"(N) : "memory");
}
__device__ __forceinline__ void ldm4(uint32_t* r, uint32_t addr) {
    asm volatile("ldmatrix.sync.aligned.m8n8.x4.shared.b16 {%0,%1,%2,%3}, [%4];"
                 : "=r"(r[0]), "=r"(r[1]), "=r"(r[2]), "=r"(r[3]) : "r"(addr) : "memory");
}
__device__ __forceinline__ void mma_bf16(float* c, const uint32_t* a, uint32_t b0,
                                         uint32_t b1) {
    asm("mma.sync.aligned.m16n8k16.row.col.f32.bf16.bf16.f32 "
        "{%0,%1,%2,%3}, {%4,%5,%6,%7}, {%8,%9}, {%0,%1,%2,%3};"
        : "+f"(c[0]), "+f"(c[1]), "+f"(c[2]), "+f"(c[3])
        : "r"(a[0]), "r"(a[1]), "r"(a[2]), "r"(a[3]), "r"(b0), "r"(b1));
}
__device__ __forceinline__ void mma_f16(float* c, const uint32_t* a, uint32_t b0,
                                        uint32_t b1) {
    asm("mma.sync.aligned.m16n8k16.row.col.f32.f16.f16.f32 "
        "{%0,%1,%2,%3}, {%4,%5,%6,%7}, {%8,%9}, {%0,%1,%2,%3};"
        : "+f"(c[0]), "+f"(c[1]), "+f"(c[2]), "+f"(c[3])
        : "r"(a[0]), "r"(a[1]), "r"(a[2]), "r"(a[3]), "r"(b0), "r"(b1));
}
__device__ __forceinline__ void split_pair(float x, float y, unsigned& hi, unsigned& lo) {
    __nv_bfloat162 h2 = __float22bfloat162_rn(make_float2(x, y));
    float2 hf = __bfloat1622float2(h2);
    __nv_bfloat162 l2 = __float22bfloat162_rn(make_float2(x - hf.x, y - hf.y));
    hi = *reinterpret_cast<unsigned*>(&h2);
    lo = *reinterpret_cast<unsigned*>(&l2);
}

// ---------------- kernel: bit-pack adjacency ----------------
__global__ __launch_bounds__(256) void bitpack_kernel(const int* __restrict__ adj) {
    int t = blockIdx.x * blockDim.x + threadIdx.x;
    const int4* p = (const int4*)adj + (size_t)t * 8;
    unsigned w = 0;
#pragma unroll
    for (int i = 0; i < 8; i++) {
        int4 v = p[i];
        w |= (v.x > 0 ? 1u : 0u) << (4 * i);
        w |= (v.y > 0 ? 1u : 0u) << (4 * i + 1);
        w |= (v.z > 0 ? 1u : 0u) << (4 * i + 2);
        w |= (v.w > 0 ? 1u : 0u) << (4 * i + 3);
    }
    g_adjbits[t] = w;
}

// ---------------- kernel: split x into bf16 hi/lo ----------------
__global__ __launch_bounds__(256) void xsplit_kernel(const float* __restrict__ x) {
    int gid = blockIdx.x * blockDim.x + threadIdx.x;
    const float4* xp = (const float4*)x + gid * 2;
    float4 v0 = xp[0], v1 = xp[1];
    float f[8] = {v0.x, v0.y, v0.z, v0.w, v1.x, v1.y, v1.z, v1.w};
    unsigned hw[4], lw[4];
#pragma unroll
    for (int i = 0; i < 4; i++) split_pair(f[2 * i], f[2 * i + 1], hw[i], lw[i]);
    *(uint4*)(g_x_hi + (size_t)gid * 8) = make_uint4(hw[0], hw[1], hw[2], hw[3]);
    *(uint4*)(g_x_lo + (size_t)gid * 8) = make_uint4(lw[0], lw[1], lw[2], lw[3]);
}

// ---------------- kernel: transpose + split W -> WT[h][o][k] ----------------
__global__ __launch_bounds__(256) void wsplit_kernel(const float* __restrict__ W) {
    const int h = blockIdx.x;
    const int t = threadIdx.x;
#pragma unroll 4
    for (int i = 0; i < 128; i++) {
        int lin = i * 256 + t;
        int o = lin >> 9, k = lin & 511;
        float v = W[((size_t)h * IN_F + k) * OUT_F + o];
        __nv_bfloat16 hb = __float2bfloat16(v);
        __nv_bfloat16 lb = __float2bfloat16(v - __bfloat162float(hb));
        size_t d = ((size_t)h * OUT_F + o) * IN_F + k;
        g_WT_hi[d] = hb;
        g_WT_lo[d] = lb;
    }
}

// ---------------- kernel: Wh = x @ W via HMMA (3-term bf16 split) ----------------
__global__ __launch_bounds__(256, 2) void wh_mma_kernel() {
    extern __shared__ __align__(16) char sm[];
    const int t = threadIdx.x;
    const int wid = t >> 5, lane = t & 31;
    const int h = blockIdx.y;
    const int nbase = blockIdx.x * RT;

    const int a_p[4] = {(t * 4) >> 9, (t * 4 + 1) >> 9, (t * 4 + 2) >> 9, (t * 4 + 3) >> 9};
    int a_r[4], a_q[4];
    const __nv_bfloat16* a_src[4];
    uint32_t a_doff[4];
#pragma unroll
    for (int i = 0; i < 4; i++) {
        int idx = t * 4 + i;
        a_r[i] = (idx >> 2) & 127;
        a_q[i] = idx & 3;
        a_src[i] = (a_p[i] ? g_x_lo : g_x_hi) + (size_t)(nbase + a_r[i]) * IN_F + a_q[i] * 8;
        a_doff[i] = (uint32_t)(a_r[i] * (ASTR * 2) + a_q[i] * 16);
    }
    int b_p[2];
    const __nv_bfloat16* b_src[2];
    uint32_t b_doff[2];
#pragma unroll
    for (int i = 0; i < 2; i++) {
        int idx = t * 2 + i;
        b_p[i] = idx >> 8;
        int br = (idx >> 2) & 63, bq = idx & 3;
        b_src[i] = (b_p[i] ? g_WT_lo : g_WT_hi) + ((size_t)h * OUT_F + br) * IN_F + bq * 8;
        b_doff[i] = (uint32_t)(br * (BSTR * 2) + bq * 16);
    }
    const uint32_t smb = smem_u32(sm);

#pragma unroll
    for (int i = 0; i < 4; i++) cp16(smb + WH_A(0, a_p[i]) + a_doff[i], a_src[i]);
#pragma unroll
    for (int i = 0; i < 2; i++) cp16(smb + WH_B(0, b_p[i]) + b_doff[i], b_src[i]);
    cp_commit();

    float acc[8][4];
#pragma unroll
    for (int j = 0; j < 8; j++)
#pragma unroll
        for (int q = 0; q < 4; q++) acc[j][q] = 0.f;

    const uint32_t aRow = (16 * wid + (lane & 15)) * (ASTR * 2) + (lane >> 4) * 16;
    const uint32_t bRow = (lane & 7) * (BSTR * 2) + (lane >> 3) * 16;

    for (int c = 0; c < NCH_W; c++) {
        const int p = c & 1, pn = p ^ 1;
        cp_wait<0>();
        __syncthreads();
        if (c + 1 < NCH_W) {
            const int kb = (c + 1) * KC;
#pragma unroll
            for (int i = 0; i < 4; i++) cp16(smb + WH_A(pn, a_p[i]) + a_doff[i], a_src[i] + kb);
#pragma unroll
            for (int i = 0; i < 2; i++) cp16(smb + WH_B(pn, b_p[i]) + b_doff[i], b_src[i] + kb);
            cp_commit();
        }
        uint32_t afh[2][4], afl[2][4];
        ldm4(afh[0], smb + WH_A(p, 0) + aRow);
        ldm4(afh[1], smb + WH_A(p, 0) + aRow + 32);
        ldm4(afl[0], smb + WH_A(p, 1) + aRow);
        ldm4(afl[1], smb + WH_A(p, 1) + aRow + 32);
#pragma unroll
        for (int j = 0; j < 8; j++) {
            uint32_t bh[4], bl[4];
            ldm4(bh, smb + WH_B(p, 0) + j * 8 * (BSTR * 2) + bRow);
            ldm4(bl, smb + WH_B(p, 1) + j * 8 * (BSTR * 2) + bRow);
            mma_bf16(acc[j], afh[0], bh[0], bh[1]);
            mma_bf16(acc[j], afh[0], bl[0], bl[1]);
            mma_bf16(acc[j], afl[0], bh[0], bh[1]);
            mma_bf16(acc[j], afh[1], bh[2], bh[3]);
            mma_bf16(acc[j], afh[1], bl[2], bl[3]);
            mma_bf16(acc[j], afl[1], bh[2], bh[3]);
        }
    }

    const int g = lane >> 2;
    const int row0 = nbase + 16 * wid + g;
    float* o0 = g_Wh + ((size_t)h * N_NODES + row0) * OUT_F + (lane & 3) * 2;
    float* o1 = o0 + 8 * OUT_F;
#pragma unroll
    for (int j = 0; j < 8; j++) {
        *(float2*)(o0 + j * 8) = make_float2(acc[j][0], acc[j][1]);
        *(float2*)(o1 + j * 8) = make_float2(acc[j][2], acc[j][3]);
    }
}

// ---------------- kernel: f1/f2 + unshifted exp tables ----------------
__global__ void attn_vec_kernel(const float* __restrict__ a1,
                                const float* __restrict__ a2) {
    int gw = (blockIdx.x * blockDim.x + threadIdx.x) >> 5;
    int lane = threadIdx.x & 31;
    if (gw >= HEADS * N_NODES) return;
    int h = gw >> 12;
    int n = gw & (N_NODES - 1);
    const float* whp = &g_Wh[(h * N_NODES + n) * OUT_F];
    float w0 = whp[lane], w1 = whp[lane + 32];
    float s1 = w0 * a1[h * OUT_F + lane] + w1 * a1[h * OUT_F + lane + 32];
    float s2 = w0 * a2[h * OUT_F + lane] + w1 * a2[h * OUT_F + lane + 32];
#pragma unroll
    for (int off = 16; off; off >>= 1) {
        s1 += __shfl_xor_sync(0xffffffffu, s1, off);
        s2 += __shfl_xor_sync(0xffffffffu, s2, off);
    }
    if (lane == 0) {
        int idx = h * N_NODES + n;
        g_f1[idx] = s1;
        g_f2[idx] = s2;
        g_P2[idx] = expf(s2);
        g_Q2[idx] = expf(ALPHA * s2);
    }
}

// ---------------- kernel: per-head max of f2 ----------------
__global__ __launch_bounds__(256) void maxf2_kernel() {
    __shared__ float red[256];
    const int h = blockIdx.x, t = threadIdx.x;
    float m = -3.4e38f;
#pragma unroll
    for (int i = 0; i < 16; i++) m = fmaxf(m, g_f2[h * N_NODES + t + i * 256]);
    red[t] = m;
    __syncthreads();
    for (int s = 128; s; s >>= 1) {
        if (t < s) red[t] = fmaxf(red[t], red[t + s]);
        __syncthreads();
    }
    if (t == 0) g_mx[h] = red[0];
}

// ---------------- kernel: shifted P1/Q1 ----------------
__global__ __launch_bounds__(256) void exp1_kernel() {
    int idx = blockIdx.x * blockDim.x + threadIdx.x;
    int h = idx >> 12;
    float f1 = g_f1[idx];
    float s = f1 + g_mx[h];
    float M = s > 0.f ? s : ALPHA * s;
    g_P1[idx] = expf(f1 - M);
    g_Q1[idx] = expf(ALPHA * f1 - M);
}

// ---------------- kernel: transpose + fp16 convert of Wh ----------------
__global__ __launch_bounds__(256) void whT_split_kernel() {
    __shared__ float T[64 * 65];
    const int h = blockIdx.y;
    const int mb = blockIdx.x * 64;
    const int t = threadIdx.x;
    const float* src = g_Wh + ((size_t)h * N_NODES + mb) * OUT_F;
#pragma unroll
    for (int i = 0; i < 16; i++) {
        int lin = t + i * 256;
        int m = lin >> 6, o = lin & 63;
        T[m * 65 + o] = src[lin];
    }
    __syncthreads();
#pragma unroll
    for (int i = 0; i < 8; i++) {
        int lin = t + i * 256;
        int o = lin >> 5, mp = lin & 31;
        __half2 h2 = __floats2half2_rn(T[(2 * mp) * 65 + o], T[(2 * mp + 1) * 65 + o]);
        size_t dst = ((size_t)h * OUT_F + o) * N_NODES + mb + 2 * mp;
        *reinterpret_cast<unsigned*>(&g_WhT_h16[dst]) = *reinterpret_cast<unsigned*>(&h2);
    }
}

// ---------------- kernel: fp16 HMMA fused masked-softmax aggregation ----------------
// 64 rows x 64 cols per CTA; KC2=64 m per chunk; 8 warps: (wid&3)->rows, (wid>>2)->cols
__global__ __launch_bounds__(256, 3) void gat_mma_kernel(float* __restrict__ out) {
    extern __shared__ __align__(16) char sm[];
    const int t = threadIdx.x;
    const int wid = t >> 5, lane = t & 31;
    const int h = blockIdx.y;
    const int nbase = blockIdx.x * GAT_RT;
    const int hN = h * N_NODES;
    const uint32_t smb = smem_u32(sm);

    // w-gen assignment: row rr (0..63), quarter q -> 16 m's
    const int rr = t >> 2;
    const int q = t & 3;
    const int grow = nbase + rr;
    const float F1r = g_f1[hN + grow];
    const float P1r = g_P1[hN + grow];
    const float Q1r = g_Q1[hN + grow];
    const unsigned* adjrow = g_adjbits + (size_t)grow * (N_NODES / 32);
    float Dacc = 0.f;

    const __half* whTh = g_WhT_h16 + ((size_t)h * OUT_F) * N_NODES;

    // B staging: 512 quads ([64 o][8 quads]), 2 per thread
    const __half* b_src[2];
    uint32_t b_doff[2];
#pragma unroll
    for (int i = 0; i < 2; i++) {
        int idx = t * 2 + i;
        int br = idx >> 3, bq = idx & 7;
        b_src[i] = whTh + (size_t)br * N_NODES + bq * 8;
        b_doff[i] = (uint32_t)(br * (AST2 * 2) + bq * 16);
    }

    // w-gen chunk cn -> A buffer buf (16 fp16 weights per thread)
    auto wgen = [&](int cn, int buf) {
        const int mb = cn * KC2 + q * 16;
        const unsigned aw = adjrow[cn * 2 + (q >> 1)];
        const int bitbase = (q & 1) * 16;
        unsigned hp[8];
#pragma unroll
        for (int g4 = 0; g4 < 2; g4++) {
            float4 f2a = *(const float4*)(g_f2 + hN + mb + g4 * 8);
            float4 f2b = *(const float4*)(g_f2 + hN + mb + g4 * 8 + 4);
            float4 p2a = *(const float4*)(g_P2 + hN + mb + g4 * 8);
            float4 p2b = *(const float4*)(g_P2 + hN + mb + g4 * 8 + 4);
            float4 q2a = *(const float4*)(g_Q2 + hN + mb + g4 * 8);
            float4 q2b = *(const float4*)(g_Q2 + hN + mb + g4 * 8 + 4);
            float fv[8] = {f2a.x, f2a.y, f2a.z, f2a.w, f2b.x, f2b.y, f2b.z, f2b.w};
            float pv[8] = {p2a.x, p2a.y, p2a.z, p2a.w, p2b.x, p2b.y, p2b.z, p2b.w};
            float qv[8] = {q2a.x, q2a.y, q2a.z, q2a.w, q2b.x, q2b.y, q2b.z, q2b.w};
            float wv[8];
#pragma unroll
            for (int e = 0; e < 8; e++) {
                int bit = bitbase + g4 * 8 + e;
                float pos = F1r + fv[e];
                float w = (pos > 0.f) ? (P1r * pv[e]) : (Q1r * qv[e]);
                w = ((aw >> bit) & 1u) ? w : 0.f;
                Dacc += w;
                wv[e] = w;
            }
#pragma unroll
            for (int e = 0; e < 4; e++) {
                __half2 h2 = __floats2half2_rn(wv[2 * e], wv[2 * e + 1]);
                hp[g4 * 4 + e] = *reinterpret_cast<unsigned*>(&h2);
            }
        }
        const uint32_t dst = smb + GA_A(buf) + rr * (AST2 * 2) + q * 32;
        asm volatile("st.shared.v4.b32 [%0], {%1, %2, %3, %4};"
                     :: "r"(dst), "r"(hp[0]), "r"(hp[1]), "r"(hp[2]), "r"(hp[3]) : "memory");
        asm volatile("st.shared.v4.b32 [%0], {%1, %2, %3, %4};"
                     :: "r"(dst + 16), "r"(hp[4]), "r"(hp[5]), "r"(hp[6]), "r"(hp[7])
                     : "memory");
    };

    // prologue
#pragma unroll
    for (int i = 0; i < 2; i++) cp16(smb + GA_B(0) + b_doff[i], b_src[i]);
    cp_commit();
    wgen(0, 0);
    cp_wait<0>();
    __syncthreads();

    float acc[4][4];
#pragma unroll
    for (int j = 0; j < 4; j++)
#pragma unroll
        for (int e = 0; e < 4; e++) acc[j][e] = 0.f;

    const uint32_t aRow = (16 * (wid & 3) + (lane & 15)) * (AST2 * 2) + (lane >> 4) * 16;
    const int jbase = (wid >> 2) * 32;   // output-column base
    const uint32_t bOff = (jbase + (lane & 7)) * (AST2 * 2) + (lane >> 3) * 16;

    for (int c = 0; c < NCH2; c++) {
        const int p = c & 1, pn = p ^ 1;
        if (c + 1 < NCH2) {
            const int mb2 = (c + 1) * KC2;
#pragma unroll
            for (int i = 0; i < 2; i++) cp16(smb + GA_B(pn) + b_doff[i], b_src[i] + mb2);
            cp_commit();
        }
        uint32_t af[4][4];
        ldm4(af[0], smb + GA_A(p) + aRow);
        ldm4(af[1], smb + GA_A(p) + aRow + 32);
        ldm4(af[2], smb + GA_A(p) + aRow + 64);
        ldm4(af[3], smb + GA_A(p) + aRow + 96);
#pragma unroll
        for (int j = 0; j < 4; j++) {
            uint32_t b0[4], b1[4];
            ldm4(b0, smb + GA_B(p) + j * 8 * (AST2 * 2) + bOff);
            ldm4(b1, smb + GA_B(p) + j * 8 * (AST2 * 2) + bOff + 64);
            mma_f16(acc[j], af[0], b0[0], b0[1]);
            mma_f16(acc[j], af[1], b0[2], b0[3]);
            mma_f16(acc[j], af[2], b1[0], b1[1]);
            mma_f16(acc[j], af[3], b1[2], b1[3]);
        }
        if (c + 1 < NCH2) wgen(c + 1, pn);
        cp_wait<0>();
        __syncthreads();
    }

    float* Dsh = (float*)(sm + GA_DSH);
    Dsh[t] = Dacc;
    __syncthreads();

    const int g = lane >> 2;
    const int row0 = 16 * (wid & 3) + g;
    const int row1 = row0 + 8;
    const float inv0 =
        1.0f / (Dsh[4 * row0] + Dsh[4 * row0 + 1] + Dsh[4 * row0 + 2] + Dsh[4 * row0 + 3]);
    const float inv1 =
        1.0f / (Dsh[4 * row1] + Dsh[4 * row1 + 1] + Dsh[4 * row1 + 2] + Dsh[4 * row1 + 3]);
    float* o0 = out + (size_t)(nbase + row0) * (HEADS * OUT_F) + h * OUT_F + jbase +
                (lane & 3) * 2;
    float* o1 = out + (size_t)(nbase + row1) * (HEADS * OUT_F) + h * OUT_F + jbase +
                (lane & 3) * 2;
#pragma unroll
    for (int j = 0; j < 4; j++) {
        *(float2*)(o0 + j * 8) = make_float2(acc[j][0] * inv0, acc[j][1] * inv0);
        *(float2*)(o1 + j * 8) = make_float2(acc[j][2] * inv1, acc[j][3] * inv1);
    }
}

// ---------------- launch ----------------
extern "C" void kernel_launch(void* const* d_in, const int* in_sizes, int n_in,
                              void* d_out, int out_size) {
    const float* x   = (const float*)d_in[0];
    const int*   adj = (const int*)d_in[1];
    const float* W   = (const float*)d_in[2];
    const float* a1  = (const float*)d_in[3];
    const float* a2  = (const float*)d_in[4];
    float* out = (float*)d_out;

    cudaFuncSetAttribute(wh_mma_kernel, cudaFuncAttributeMaxDynamicSharedMemorySize,
                         WH_SMEM);
    cudaFuncSetAttribute(gat_mma_kernel, cudaFuncAttributeMaxDynamicSharedMemorySize,
                         GA_SMEM);

    bitpack_kernel<<<(N_NODES * N_NODES / 32) / 256, 256>>>(adj);
    xsplit_kernel<<<(N_NODES * IN_F) / (256 * 8), 256>>>(x);
    wsplit_kernel<<<HEADS, 256>>>(W);

    dim3 gW(N_NODES / RT, HEADS);
    wh_mma_kernel<<<gW, 256, WH_SMEM>>>();

    attn_vec_kernel<<<(HEADS * N_NODES * 32) / 256, 256>>>(a1, a2);
    maxf2_kernel<<<HEADS, 256>>>();
    exp1_kernel<<<(HEADS * N_NODES) / 256, 256>>>();

    dim3 gT(N_NODES / 64, HEADS);
    whT_split_kernel<<<gT, 256>>>();

    dim3 gD(N_NODES / GAT_RT, HEADS);
    gat_mma_kernel<<<gD, 256, GA_SMEM>>>(out);
}